// round 1
// baseline (speedup 1.0000x reference)
#include <cuda_runtime.h>
#include <math.h>

#define BB   8
#define SS   1024
#define EE   1024
#define HH   16
#define DHH  64
#define HIDD 4096
#define MTOK (BB*SS)   // 8192 token rows

// ---------------- scratch (static device globals; no runtime alloc) -------
__device__ float g_q  [(size_t)MTOK*EE];
__device__ float g_k  [(size_t)MTOK*EE];
__device__ float g_v  [(size_t)MTOK*EE];
__device__ float g_o  [(size_t)MTOK*EE];
__device__ float g_h2 [(size_t)MTOK*EE];
__device__ float g_a  [(size_t)MTOK*EE];
__device__ float g_hid[(size_t)MTOK*HIDD];
__device__ float g_f  [(size_t)MTOK*EE];

__device__ __forceinline__ float gelu_exact(float x) {
    return 0.5f * x * (1.0f + erff(x * 0.70710678118654752f));
}

// ---------------------------------------------------------------------------
// GEMM: C[M,N] = A[M,K] @ W[N,K]^T  (nn.Linear layout), templated epilogue
// EPI: 0 = none, 1 = +bias, 2 = +bias then exact GELU, 3 = +res (residual add)
// Tiles: 64x64x16, 256 threads, 4x4 per thread, float4 smem reads.
// ---------------------------------------------------------------------------
template<int EPI>
__global__ void __launch_bounds__(256) gemm_kernel(
    const float* __restrict__ A, const float* __restrict__ W,
    const float* __restrict__ bias, const float* __restrict__ res,
    float* __restrict__ C, int M, int N, int K)
{
    const int BK = 16;
    __shared__ float As[BK][64 + 4];
    __shared__ float Ws[BK][64 + 4];

    const int tid = threadIdx.x;
    const int tx  = tid & 15;        // 0..15  -> n micro
    const int ty  = tid >> 4;        // 0..15  -> m micro
    const int m0  = blockIdx.y << 6;
    const int n0  = blockIdx.x << 6;

    const int lk = tid & 15;         // k within tile
    const int lm = tid >> 4;         // row within tile (step 16)

    const float* Ap = A + (size_t)(m0 + lm) * K + lk;
    const float* Wp = W + (size_t)(n0 + lm) * K + lk;

    float acc[4][4] = {};

    for (int k0 = 0; k0 < K; k0 += BK) {
        __syncthreads();
#pragma unroll
        for (int r = 0; r < 4; r++)
            As[lk][lm + 16*r] = Ap[(size_t)(16*r) * K + k0];
#pragma unroll
        for (int r = 0; r < 4; r++)
            Ws[lk][lm + 16*r] = Wp[(size_t)(16*r) * K + k0];
        __syncthreads();

#pragma unroll
        for (int kk = 0; kk < BK; kk++) {
            float4 a4 = *(const float4*)&As[kk][ty * 4];
            float4 w4 = *(const float4*)&Ws[kk][tx * 4];
            float av[4] = {a4.x, a4.y, a4.z, a4.w};
            float wv[4] = {w4.x, w4.y, w4.z, w4.w};
#pragma unroll
            for (int i = 0; i < 4; i++)
#pragma unroll
                for (int j = 0; j < 4; j++)
                    acc[i][j] += av[i] * wv[j];
        }
    }

    const int cn = n0 + tx * 4;
    float4 bv = make_float4(0.f, 0.f, 0.f, 0.f);
    if (EPI == 1 || EPI == 2) bv = *(const float4*)&bias[cn];

#pragma unroll
    for (int i = 0; i < 4; i++) {
        const int row = m0 + ty * 4 + i;
        float v0 = acc[i][0], v1 = acc[i][1], v2 = acc[i][2], v3 = acc[i][3];
        if (EPI == 1 || EPI == 2) { v0 += bv.x; v1 += bv.y; v2 += bv.z; v3 += bv.w; }
        if (EPI == 2) {
            v0 = gelu_exact(v0); v1 = gelu_exact(v1);
            v2 = gelu_exact(v2); v3 = gelu_exact(v3);
        }
        if (EPI == 3) {
            float4 r4 = *(const float4*)&res[(size_t)row * N + cn];
            v0 += r4.x; v1 += r4.y; v2 += r4.z; v3 += r4.w;
        }
        *(float4*)&C[(size_t)row * N + cn] = make_float4(v0, v1, v2, v3);
    }
}

// ---------------------------------------------------------------------------
// Fused masked flash-attention.
// grid = (S/64, H, B), 256 threads. One CTA: one (b,h) x 64 query rows.
// Faithful to: aw = softmax(s*m); out = aw*m / (sum(aw*m)+1e-20)
//   == e_j*m_j / (sum_k e_k*m_k + tiny), e_j = exp(s_j*m_j - max(s*m))
// ---------------------------------------------------------------------------
__global__ void __launch_bounds__(256) attn_kernel(const float* __restrict__ mask)
{
    extern __shared__ float smn[];
    float (*Qs)[68] = (float(*)[68])(smn);               // [d][i]
    float (*Ks)[68] = (float(*)[68])(smn + 64 * 68);     // [d][j]
    float (*Vs)[68] = (float(*)[68])(smn + 2 * 64 * 68); // [j][d]
    float (*Ps)[68] = (float(*)[68])(smn + 3 * 64 * 68); // [i][j]

    const int qt = blockIdx.x, hh = blockIdx.y, b = blockIdx.z;
    const int tid = threadIdx.x;
    const int tx  = tid & 15;       // key-col / d-col micro
    const int ty  = tid >> 4;       // query-row micro
    const int col0 = hh * 64;

    // load Q tile transposed: Qs[d][i]
    {
        const int d  = tid & 63;
        const int i0 = tid >> 6;    // 0..3
        const size_t qbase = ((size_t)b * SS + (size_t)qt * 64) * EE + col0;
#pragma unroll
        for (int p = 0; p < 16; p++) {
            int i = i0 + 4 * p;
            Qs[d][i] = g_q[qbase + (size_t)i * EE + d];
        }
    }

    float O[4][4] = {};
    float rmax[4] = {-1e30f, -1e30f, -1e30f, -1e30f};
    float rsum[4] = {};
    const int qg = qt * 64 + ty * 4;

    for (int kt = 0; kt < 16; kt++) {
        __syncthreads();
        {
            const int d  = tid & 63;
            const int j0 = tid >> 6;
            const size_t kb = ((size_t)b * SS + (size_t)kt * 64) * EE + col0;
#pragma unroll
            for (int p = 0; p < 16; p++) {
                int j = j0 + 4 * p;
                Ks[d][j] = g_k[kb + (size_t)j * EE + d];
                Vs[j][d] = g_v[kb + (size_t)j * EE + d];
            }
        }
        __syncthreads();

        // scores = Q K^T
        float sc[4][4] = {};
#pragma unroll 16
        for (int d = 0; d < 64; d++) {
            float4 q4 = *(const float4*)&Qs[d][ty * 4];
            float4 k4 = *(const float4*)&Ks[d][tx * 4];
            float qv[4] = {q4.x, q4.y, q4.z, q4.w};
            float kv[4] = {k4.x, k4.y, k4.z, k4.w};
#pragma unroll
            for (int i = 0; i < 4; i++)
#pragma unroll
                for (int j = 0; j < 4; j++)
                    sc[i][j] += qv[i] * kv[j];
        }

        // online masked softmax (per query row i)
#pragma unroll
        for (int i = 0; i < 4; i++) {
            float4 m4 = *(const float4*)&mask[((size_t)b * SS + qg + i) * SS + kt * 64 + tx * 4];
            float sm0 = sc[i][0] * 0.125f * m4.x;
            float sm1 = sc[i][1] * 0.125f * m4.y;
            float sm2 = sc[i][2] * 0.125f * m4.z;
            float sm3 = sc[i][3] * 0.125f * m4.w;
            float tmax = fmaxf(fmaxf(sm0, sm1), fmaxf(sm2, sm3));
#pragma unroll
            for (int ofs = 1; ofs < 16; ofs <<= 1)
                tmax = fmaxf(tmax, __shfl_xor_sync(0xffffffffu, tmax, ofs));
            float newmax = fmaxf(rmax[i], tmax);
            float corr = __expf(rmax[i] - newmax);
            rmax[i] = newmax;
            float e0 = __expf(sm0 - newmax) * m4.x;
            float e1 = __expf(sm1 - newmax) * m4.y;
            float e2 = __expf(sm2 - newmax) * m4.z;
            float e3 = __expf(sm3 - newmax) * m4.w;
            float ts = e0 + e1 + e2 + e3;
#pragma unroll
            for (int ofs = 1; ofs < 16; ofs <<= 1)
                ts += __shfl_xor_sync(0xffffffffu, ts, ofs);
            rsum[i] = rsum[i] * corr + ts;
#pragma unroll
            for (int j = 0; j < 4; j++) O[i][j] *= corr;
            *(float4*)&Ps[ty * 4 + i][tx * 4] = make_float4(e0, e1, e2, e3);
        }
        __syncthreads();

        // O += P @ V
#pragma unroll 8
        for (int j = 0; j < 64; j++) {
            float4 v4 = *(const float4*)&Vs[j][tx * 4];
            float vv[4] = {v4.x, v4.y, v4.z, v4.w};
            float p0 = Ps[ty * 4 + 0][j];
            float p1 = Ps[ty * 4 + 1][j];
            float p2 = Ps[ty * 4 + 2][j];
            float p3 = Ps[ty * 4 + 3][j];
#pragma unroll
            for (int jj = 0; jj < 4; jj++) {
                O[0][jj] += p0 * vv[jj];
                O[1][jj] += p1 * vv[jj];
                O[2][jj] += p2 * vv[jj];
                O[3][jj] += p3 * vv[jj];
            }
        }
    }

    // normalize + store (head-stacked layout [B,S,E], cols = h*64+d)
#pragma unroll
    for (int i = 0; i < 4; i++) {
        float inv = 1.0f / (rsum[i] + 1e-20f);
        *(float4*)&g_o[((size_t)b * SS + qg + i) * EE + col0 + tx * 4] =
            make_float4(O[i][0] * inv, O[i][1] * inv, O[i][2] * inv, O[i][3] * inv);
    }
}

// ---------------------------------------------------------------------------
// LayerNorm over E=1024. One CTA per row, 256 threads (4 elems each).
// useF: out = LN(x + f * gate)   with gate[b,s] = mask[b, S-1, s]
// else: out = LN(x)
// ---------------------------------------------------------------------------
__global__ void __launch_bounds__(256) ln_kernel(
    const float* __restrict__ x, const float* __restrict__ f,
    const float* __restrict__ mask, const float* __restrict__ gamma,
    const float* __restrict__ beta, float* __restrict__ out, int useF)
{
    const int row = blockIdx.x;
    const int tid = threadIdx.x;

    float4 v4 = *(const float4*)&x[(size_t)row * EE + tid * 4];
    float v[4] = {v4.x, v4.y, v4.z, v4.w};

    if (useF) {
        const int b = row / SS, s = row % SS;
        const float gate = mask[((size_t)b * SS + (SS - 1)) * SS + s];
        float4 f4 = *(const float4*)&f[(size_t)row * EE + tid * 4];
        v[0] += f4.x * gate; v[1] += f4.y * gate;
        v[2] += f4.z * gate; v[3] += f4.w * gate;
    }

    float s1 = v[0] + v[1] + v[2] + v[3];
    float s2 = v[0]*v[0] + v[1]*v[1] + v[2]*v[2] + v[3]*v[3];
#pragma unroll
    for (int ofs = 16; ofs >= 1; ofs >>= 1) {
        s1 += __shfl_xor_sync(0xffffffffu, s1, ofs);
        s2 += __shfl_xor_sync(0xffffffffu, s2, ofs);
    }
    __shared__ float red1[8], red2[8];
    if ((tid & 31) == 0) { red1[tid >> 5] = s1; red2[tid >> 5] = s2; }
    __syncthreads();
    float t1 = 0.f, t2 = 0.f;
#pragma unroll
    for (int w = 0; w < 8; w++) { t1 += red1[w]; t2 += red2[w]; }

    const float mean = t1 * (1.0f / EE);
    const float var  = t2 * (1.0f / EE) - mean * mean;
    const float inv  = rsqrtf(var + 1e-5f);

    float4 g4 = *(const float4*)&gamma[tid * 4];
    float4 b4 = *(const float4*)&beta[tid * 4];
    float4 o4;
    o4.x = (v[0] - mean) * inv * g4.x + b4.x;
    o4.y = (v[1] - mean) * inv * g4.y + b4.y;
    o4.z = (v[2] - mean) * inv * g4.z + b4.z;
    o4.w = (v[3] - mean) * inv * g4.w + b4.w;
    *(float4*)&out[(size_t)row * EE + tid * 4] = o4;
}

// ---------------------------------------------------------------------------
extern "C" void kernel_launch(void* const* d_in, const int* in_sizes, int n_in,
                              void* d_out, int out_size)
{
    const float* h    = (const float*)d_in[0];
    const float* mask = (const float*)d_in[1];
    const float* wq   = (const float*)d_in[2];
    const float* wk   = (const float*)d_in[3];
    const float* wv   = (const float*)d_in[4];
    const float* wmh  = (const float*)d_in[5];
    const float* g1   = (const float*)d_in[6];
    const float* be1  = (const float*)d_in[7];
    const float* w1   = (const float*)d_in[8];
    const float* b1   = (const float*)d_in[9];
    const float* w2   = (const float*)d_in[10];
    const float* b2   = (const float*)d_in[11];
    const float* g2   = (const float*)d_in[12];
    const float* be2  = (const float*)d_in[13];
    float* out = (float*)d_out;

    float *q, *k, *v, *o, *h2, *a, *hid, *f;
    cudaGetSymbolAddress((void**)&q,   g_q);
    cudaGetSymbolAddress((void**)&k,   g_k);
    cudaGetSymbolAddress((void**)&v,   g_v);
    cudaGetSymbolAddress((void**)&o,   g_o);
    cudaGetSymbolAddress((void**)&h2,  g_h2);
    cudaGetSymbolAddress((void**)&a,   g_a);
    cudaGetSymbolAddress((void**)&hid, g_hid);
    cudaGetSymbolAddress((void**)&f,   g_f);

    const int ATTN_SMEM = 4 * 64 * 68 * (int)sizeof(float);   // 69,632 B
    cudaFuncSetAttribute(attn_kernel, cudaFuncAttributeMaxDynamicSharedMemorySize, ATTN_SMEM);

    dim3 blk(256);
    dim3 gE(EE / 64, MTOK / 64);        // (16, 128)
    dim3 gHid(HIDD / 64, MTOK / 64);    // (64, 128)

    // QKV projections
    gemm_kernel<0><<<gE, blk>>>(h, wq, nullptr, nullptr, q, MTOK, EE, EE);
    gemm_kernel<0><<<gE, blk>>>(h, wk, nullptr, nullptr, k, MTOK, EE, EE);
    gemm_kernel<0><<<gE, blk>>>(h, wv, nullptr, nullptr, v, MTOK, EE, EE);

    // fused masked flash attention -> g_o (head-stacked)
    attn_kernel<<<dim3(SS / 64, HH, BB), blk, ATTN_SMEM>>>(mask);

    // mh projection + residual add of h
    gemm_kernel<3><<<gE, blk>>>(o, wmh, nullptr, h, h2, MTOK, EE, EE);

    // attn_norm
    ln_kernel<<<MTOK, 256>>>(h2, nullptr, nullptr, g1, be1, a, 0);

    // FFN
    gemm_kernel<2><<<gHid, blk>>>(a, w1, b1, nullptr, hid, MTOK, HIDD, EE);
    gemm_kernel<1><<<gE,   blk>>>(hid, w2, b2, nullptr, f, MTOK, EE, HIDD);

    // gated residual + ffn_norm -> out
    ln_kernel<<<MTOK, 256>>>(a, f, mask, g2, be2, out, 1);
}

// round 3
// speedup vs baseline: 2.2010x; 2.2010x over previous
#include <cuda_runtime.h>
#include <cuda_bf16.h>
#include <math.h>
#include <stdint.h>

#define BB   8
#define SS   1024
#define EE   1024
#define HH   16
#define DHH  64
#define HIDD 4096
#define MTOK (BB*SS)   // 8192 token rows

// ---------------- fp32 scratch ---------------------------------------------
__device__ float g_q  [(size_t)MTOK*EE];
__device__ float g_k  [(size_t)MTOK*EE];
__device__ float g_v  [(size_t)MTOK*EE];
__device__ float g_o  [(size_t)MTOK*EE];
__device__ float g_h2 [(size_t)MTOK*EE];
__device__ float g_a  [(size_t)MTOK*EE];
__device__ float g_hid[(size_t)MTOK*HIDD];
__device__ float g_f  [(size_t)MTOK*EE];

// ---------------- bf16 split scratch (hi/lo) --------------------------------
__device__ __nv_bfloat16 g_hb_h [(size_t)MTOK*EE],  g_hb_l [(size_t)MTOK*EE];
__device__ __nv_bfloat16 g_ob_h [(size_t)MTOK*EE],  g_ob_l [(size_t)MTOK*EE];
__device__ __nv_bfloat16 g_ab_h [(size_t)MTOK*EE],  g_ab_l [(size_t)MTOK*EE];
__device__ __nv_bfloat16 g_hidb_h[(size_t)MTOK*HIDD], g_hidb_l[(size_t)MTOK*HIDD];
__device__ __nv_bfloat16 g_wqb_h[(size_t)EE*EE],   g_wqb_l[(size_t)EE*EE];
__device__ __nv_bfloat16 g_wkb_h[(size_t)EE*EE],   g_wkb_l[(size_t)EE*EE];
__device__ __nv_bfloat16 g_wvb_h[(size_t)EE*EE],   g_wvb_l[(size_t)EE*EE];
__device__ __nv_bfloat16 g_wmb_h[(size_t)EE*EE],   g_wmb_l[(size_t)EE*EE];
__device__ __nv_bfloat16 g_w1b_h[(size_t)HIDD*EE], g_w1b_l[(size_t)HIDD*EE];
__device__ __nv_bfloat16 g_w2b_h[(size_t)EE*HIDD], g_w2b_l[(size_t)EE*HIDD];

__device__ __forceinline__ float gelu_exact(float x) {
    return 0.5f * x * (1.0f + erff(x * 0.70710678118654752f));
}

// ============================ PTX helpers (sm_100-safe) =====================
__device__ __forceinline__ uint32_t smem_u32(const void* p) {
    uint32_t a;
    asm("{ .reg .u64 t; cvta.to.shared.u64 t, %1; cvt.u32.u64 %0, t; }"
        : "=r"(a) : "l"(p));
    return a;
}
__device__ __forceinline__ void cp16(uint32_t s, const void* g) {
    asm volatile("cp.async.cg.shared.global [%0], [%1], 16;" :: "r"(s), "l"(g));
}
__device__ __forceinline__ void cp_commit() {
    asm volatile("cp.async.commit_group;" ::: "memory");
}
template<int N>
__device__ __forceinline__ void cp_wait() {
    asm volatile("cp.async.wait_group %0;" :: "n"(N) : "memory");
}
__device__ __forceinline__ void ldsm4(uint32_t& r0, uint32_t& r1,
                                      uint32_t& r2, uint32_t& r3, uint32_t a) {
    asm volatile("ldmatrix.sync.aligned.m8n8.x4.shared.b16 {%0,%1,%2,%3}, [%4];"
                 : "=r"(r0), "=r"(r1), "=r"(r2), "=r"(r3) : "r"(a));
}
__device__ __forceinline__ void mma16816(float* d, const uint32_t* a, const uint32_t* b) {
    asm volatile(
        "mma.sync.aligned.m16n8k16.row.col.f32.bf16.bf16.f32 "
        "{%0,%1,%2,%3}, {%4,%5,%6,%7}, {%8,%9}, {%0,%1,%2,%3};"
        : "+f"(d[0]), "+f"(d[1]), "+f"(d[2]), "+f"(d[3])
        : "r"(a[0]), "r"(a[1]), "r"(a[2]), "r"(a[3]), "r"(b[0]), "r"(b[1]));
}

// ============================================================================
// split: fp32 x -> bf16 hi + bf16 lo   (x ~= hi + lo)
// ============================================================================
__global__ void __launch_bounds__(256) split_kernel(
    const float* __restrict__ x,
    __nv_bfloat16* __restrict__ hi, __nv_bfloat16* __restrict__ lo, int n4)
{
    int i = blockIdx.x * 256 + threadIdx.x;
    if (i >= n4) return;
    float4 v = ((const float4*)x)[i];
    __nv_bfloat16 h0 = __float2bfloat16(v.x);
    __nv_bfloat16 h1 = __float2bfloat16(v.y);
    __nv_bfloat16 h2 = __float2bfloat16(v.z);
    __nv_bfloat16 h3 = __float2bfloat16(v.w);
    __nv_bfloat16 l0 = __float2bfloat16(v.x - __bfloat162float(h0));
    __nv_bfloat16 l1 = __float2bfloat16(v.y - __bfloat162float(h1));
    __nv_bfloat16 l2 = __float2bfloat16(v.z - __bfloat162float(h2));
    __nv_bfloat16 l3 = __float2bfloat16(v.w - __bfloat162float(h3));
    ((__nv_bfloat162*)hi)[2*i]   = __halves2bfloat162(h0, h1);
    ((__nv_bfloat162*)hi)[2*i+1] = __halves2bfloat162(h2, h3);
    ((__nv_bfloat162*)lo)[2*i]   = __halves2bfloat162(l0, l1);
    ((__nv_bfloat162*)lo)[2*i+1] = __halves2bfloat162(l2, l3);
}

// ============================================================================
// HMMA GEMM: C[M,N] = A[M,K] @ W[N,K]^T  (bf16x3 split, fp32 accumulate)
// CTA 128x128, BK=32, 512 threads (16 warps, 4x4 grid of 32x32 warp tiles).
// 3-stage cp.async pipeline. EPI: 0=none, 1=+bias, 2=+bias,GELU, 3=+res
// ============================================================================
#define TM 128
#define TN 128
#define BK 32
#define ROWB 80                      // 64B data + 16B pad, conflict-free ldmatrix
#define SUBB (128 * ROWB)            // 10240 B per sub-tile
#define STAGE_B (4 * SUBB)           // 40960 B: Ahi | Alo | Whi | Wlo
#define SMEM_MMA (3 * STAGE_B)       // 122880 B

template<int EPI>
__global__ void __launch_bounds__(512, 1) gemm_mma(
    const __nv_bfloat16* __restrict__ Ahi, const __nv_bfloat16* __restrict__ Alo,
    const __nv_bfloat16* __restrict__ Whi, const __nv_bfloat16* __restrict__ Wlo,
    const float* __restrict__ bias, const float* __restrict__ res,
    float* __restrict__ C, int M, int N, int K)
{
    extern __shared__ __align__(128) char smem[];
    const uint32_t sb = smem_u32(smem);
    const int tid  = threadIdx.x;
    const int lane = tid & 31;
    const int wid  = tid >> 5;
    const int wm   = wid & 3;          // warp m-tile (32 rows)
    const int wn   = wid >> 2;         // warp n-tile (32 cols)
    const int m0   = blockIdx.y * TM;
    const int n0   = blockIdx.x * TN;

    // cp.async per-thread coords: 512 threads = 128 rows x 4 chunks of 16B
    const int lrow = tid >> 2, lc16 = tid & 3;
    const size_t   ga   = (size_t)(m0 + lrow) * K + lc16 * 8;
    const size_t   gw   = (size_t)(n0 + lrow) * K + lc16 * 8;
    const uint32_t soff = lrow * ROWB + lc16 * 16;

    // ldmatrix lane addressing
    const uint32_t a_row  = wm * 32 + (lane & 15);
    const uint32_t a_coff = (lane >> 4) * 16;
    const uint32_t b_row  = wn * 32 + ((lane >> 4) << 3) + (lane & 7);
    const uint32_t b_coff = ((lane >> 3) & 1) * 16;

    float acc[2][4][4];
#pragma unroll
    for (int mt = 0; mt < 2; mt++)
#pragma unroll
        for (int nt = 0; nt < 4; nt++)
#pragma unroll
            for (int r = 0; r < 4; r++) acc[mt][nt][r] = 0.f;

    const int nst = K / BK;

    // prologue: stage 0 and 1
#pragma unroll
    for (int s = 0; s < 2; s++) {
        const uint32_t b = sb + s * STAGE_B;
        const int k0 = s * BK;
        cp16(b + 0*SUBB + soff, Ahi + ga + k0);
        cp16(b + 1*SUBB + soff, Alo + ga + k0);
        cp16(b + 2*SUBB + soff, Whi + gw + k0);
        cp16(b + 3*SUBB + soff, Wlo + gw + k0);
        cp_commit();
    }

    int sbuf = 0;
    for (int s = 0; s < nst; s++) {
        cp_wait<1>();
        __syncthreads();

        if (s + 2 < nst) {
            const int nb = (sbuf + 2 >= 3) ? sbuf - 1 : sbuf + 2;
            const uint32_t b = sb + nb * STAGE_B;
            const int k0 = (s + 2) * BK;
            cp16(b + 0*SUBB + soff, Ahi + ga + k0);
            cp16(b + 1*SUBB + soff, Alo + ga + k0);
            cp16(b + 2*SUBB + soff, Whi + gw + k0);
            cp16(b + 3*SUBB + soff, Wlo + gw + k0);
            cp_commit();
        }

        const uint32_t bbase = sb + sbuf * STAGE_B;
#pragma unroll
        for (int kk = 0; kk < 2; kk++) {
            uint32_t ah[2][4], al[2][4];
#pragma unroll
            for (int mt = 0; mt < 2; mt++) {
                uint32_t ad = bbase + (a_row + mt * 16) * ROWB + a_coff + kk * 32;
                ldsm4(ah[mt][0], ah[mt][1], ah[mt][2], ah[mt][3], ad);
                ldsm4(al[mt][0], al[mt][1], al[mt][2], al[mt][3], ad + SUBB);
            }
            uint32_t bh[2][4], bl[2][4];
#pragma unroll
            for (int np = 0; np < 2; np++) {
                uint32_t bd = bbase + 2*SUBB + (b_row + np * 16) * ROWB + b_coff + kk * 32;
                ldsm4(bh[np][0], bh[np][1], bh[np][2], bh[np][3], bd);
                ldsm4(bl[np][0], bl[np][1], bl[np][2], bl[np][3], bd + SUBB);
            }
#pragma unroll
            for (int mt = 0; mt < 2; mt++)
#pragma unroll
                for (int nt = 0; nt < 4; nt++) {
                    const uint32_t* Bh = &bh[nt >> 1][(nt & 1) * 2];
                    const uint32_t* Bl = &bl[nt >> 1][(nt & 1) * 2];
                    mma16816(acc[mt][nt], ah[mt], Bh);   // hi*hi
                    mma16816(acc[mt][nt], ah[mt], Bl);   // hi*lo
                    mma16816(acc[mt][nt], al[mt], Bh);   // lo*hi
                }
        }
        __syncthreads();
        sbuf = (sbuf + 1 >= 3) ? 0 : sbuf + 1;
    }

    // ---- epilogue: straight from accumulators -----------------------------
#pragma unroll
    for (int mt = 0; mt < 2; mt++) {
        const int rowA = m0 + wm * 32 + mt * 16 + (lane >> 2);
#pragma unroll
        for (int nt = 0; nt < 4; nt++) {
            const int col = n0 + wn * 32 + nt * 8 + (lane & 3) * 2;
            float b0 = 0.f, b1 = 0.f;
            if (EPI == 1 || EPI == 2) { b0 = bias[col]; b1 = bias[col + 1]; }
#pragma unroll
            for (int half = 0; half < 2; half++) {
                const int row = rowA + half * 8;
                float v0 = acc[mt][nt][half * 2 + 0];
                float v1 = acc[mt][nt][half * 2 + 1];
                if (EPI == 1 || EPI == 2) { v0 += b0; v1 += b1; }
                if (EPI == 2) { v0 = gelu_exact(v0); v1 = gelu_exact(v1); }
                const size_t go = (size_t)row * N + col;
                if (EPI == 3) {
                    float2 r2 = *(const float2*)&res[go];
                    v0 += r2.x; v1 += r2.y;
                }
                *(float2*)&C[go] = make_float2(v0, v1);
            }
        }
    }
}

// ============================================================================
// Fused masked flash-attention (fp32, unchanged from R1)
// ============================================================================
__global__ void __launch_bounds__(256) attn_kernel(const float* __restrict__ mask)
{
    extern __shared__ float smn[];
    float (*Qs)[68] = (float(*)[68])(smn);
    float (*Ks)[68] = (float(*)[68])(smn + 64 * 68);
    float (*Vs)[68] = (float(*)[68])(smn + 2 * 64 * 68);
    float (*Ps)[68] = (float(*)[68])(smn + 3 * 64 * 68);

    const int qt = blockIdx.x, hh = blockIdx.y, b = blockIdx.z;
    const int tid = threadIdx.x;
    const int tx  = tid & 15;
    const int ty  = tid >> 4;
    const int col0 = hh * 64;

    {
        const int d  = tid & 63;
        const int i0 = tid >> 6;
        const size_t qbase = ((size_t)b * SS + (size_t)qt * 64) * EE + col0;
#pragma unroll
        for (int p = 0; p < 16; p++) {
            int i = i0 + 4 * p;
            Qs[d][i] = g_q[qbase + (size_t)i * EE + d];
        }
    }

    float O[4][4] = {};
    float rmax[4] = {-1e30f, -1e30f, -1e30f, -1e30f};
    float rsum[4] = {};
    const int qg = qt * 64 + ty * 4;

    for (int kt = 0; kt < 16; kt++) {
        __syncthreads();
        {
            const int d  = tid & 63;
            const int j0 = tid >> 6;
            const size_t kb = ((size_t)b * SS + (size_t)kt * 64) * EE + col0;
#pragma unroll
            for (int p = 0; p < 16; p++) {
                int j = j0 + 4 * p;
                Ks[d][j] = g_k[kb + (size_t)j * EE + d];
                Vs[j][d] = g_v[kb + (size_t)j * EE + d];
            }
        }
        __syncthreads();

        float sc[4][4] = {};
#pragma unroll 16
        for (int d = 0; d < 64; d++) {
            float4 q4 = *(const float4*)&Qs[d][ty * 4];
            float4 k4 = *(const float4*)&Ks[d][tx * 4];
            float qv[4] = {q4.x, q4.y, q4.z, q4.w};
            float kv[4] = {k4.x, k4.y, k4.z, k4.w};
#pragma unroll
            for (int i = 0; i < 4; i++)
#pragma unroll
                for (int j = 0; j < 4; j++)
                    sc[i][j] += qv[i] * kv[j];
        }

#pragma unroll
        for (int i = 0; i < 4; i++) {
            float4 m4 = *(const float4*)&mask[((size_t)b * SS + qg + i) * SS + kt * 64 + tx * 4];
            float sm0 = sc[i][0] * 0.125f * m4.x;
            float sm1 = sc[i][1] * 0.125f * m4.y;
            float sm2 = sc[i][2] * 0.125f * m4.z;
            float sm3 = sc[i][3] * 0.125f * m4.w;
            float tmax = fmaxf(fmaxf(sm0, sm1), fmaxf(sm2, sm3));
#pragma unroll
            for (int ofs = 1; ofs < 16; ofs <<= 1)
                tmax = fmaxf(tmax, __shfl_xor_sync(0xffffffffu, tmax, ofs));
            float newmax = fmaxf(rmax[i], tmax);
            float corr = __expf(rmax[i] - newmax);
            rmax[i] = newmax;
            float e0 = __expf(sm0 - newmax) * m4.x;
            float e1 = __expf(sm1 - newmax) * m4.y;
            float e2 = __expf(sm2 - newmax) * m4.z;
            float e3 = __expf(sm3 - newmax) * m4.w;
            float ts = e0 + e1 + e2 + e3;
#pragma unroll
            for (int ofs = 1; ofs < 16; ofs <<= 1)
                ts += __shfl_xor_sync(0xffffffffu, ts, ofs);
            rsum[i] = rsum[i] * corr + ts;
#pragma unroll
            for (int j = 0; j < 4; j++) O[i][j] *= corr;
            *(float4*)&Ps[ty * 4 + i][tx * 4] = make_float4(e0, e1, e2, e3);
        }
        __syncthreads();

#pragma unroll 8
        for (int j = 0; j < 64; j++) {
            float4 v4 = *(const float4*)&Vs[j][tx * 4];
            float vv[4] = {v4.x, v4.y, v4.z, v4.w};
            float p0 = Ps[ty * 4 + 0][j];
            float p1 = Ps[ty * 4 + 1][j];
            float p2 = Ps[ty * 4 + 2][j];
            float p3 = Ps[ty * 4 + 3][j];
#pragma unroll
            for (int jj = 0; jj < 4; jj++) {
                O[0][jj] += p0 * vv[jj];
                O[1][jj] += p1 * vv[jj];
                O[2][jj] += p2 * vv[jj];
                O[3][jj] += p3 * vv[jj];
            }
        }
    }

#pragma unroll
    for (int i = 0; i < 4; i++) {
        float inv = 1.0f / (rsum[i] + 1e-20f);
        *(float4*)&g_o[((size_t)b * SS + qg + i) * EE + col0 + tx * 4] =
            make_float4(O[i][0] * inv, O[i][1] * inv, O[i][2] * inv, O[i][3] * inv);
    }
}

// ============================================================================
// LayerNorm (unchanged from R1)
// ============================================================================
__global__ void __launch_bounds__(256) ln_kernel(
    const float* __restrict__ x, const float* __restrict__ f,
    const float* __restrict__ mask, const float* __restrict__ gamma,
    const float* __restrict__ beta, float* __restrict__ out, int useF)
{
    const int row = blockIdx.x;
    const int tid = threadIdx.x;

    float4 v4 = *(const float4*)&x[(size_t)row * EE + tid * 4];
    float v[4] = {v4.x, v4.y, v4.z, v4.w};

    if (useF) {
        const int b = row / SS, s = row % SS;
        const float gate = mask[((size_t)b * SS + (SS - 1)) * SS + s];
        float4 f4 = *(const float4*)&f[(size_t)row * EE + tid * 4];
        v[0] += f4.x * gate; v[1] += f4.y * gate;
        v[2] += f4.z * gate; v[3] += f4.w * gate;
    }

    float s1 = v[0] + v[1] + v[2] + v[3];
    float s2 = v[0]*v[0] + v[1]*v[1] + v[2]*v[2] + v[3]*v[3];
#pragma unroll
    for (int ofs = 16; ofs >= 1; ofs >>= 1) {
        s1 += __shfl_xor_sync(0xffffffffu, s1, ofs);
        s2 += __shfl_xor_sync(0xffffffffu, s2, ofs);
    }
    __shared__ float red1[8], red2[8];
    if ((tid & 31) == 0) { red1[tid >> 5] = s1; red2[tid >> 5] = s2; }
    __syncthreads();
    float t1 = 0.f, t2 = 0.f;
#pragma unroll
    for (int w = 0; w < 8; w++) { t1 += red1[w]; t2 += red2[w]; }

    const float mean = t1 * (1.0f / EE);
    const float var  = t2 * (1.0f / EE) - mean * mean;
    const float inv  = rsqrtf(var + 1e-5f);

    float4 g4 = *(const float4*)&gamma[tid * 4];
    float4 b4 = *(const float4*)&beta[tid * 4];
    float4 o4;
    o4.x = (v[0] - mean) * inv * g4.x + b4.x;
    o4.y = (v[1] - mean) * inv * g4.y + b4.y;
    o4.z = (v[2] - mean) * inv * g4.z + b4.z;
    o4.w = (v[3] - mean) * inv * g4.w + b4.w;
    *(float4*)&out[(size_t)row * EE + tid * 4] = o4;
}

// ============================================================================
static inline void split(const float* x, __nv_bfloat16* hi, __nv_bfloat16* lo, size_t n)
{
    int n4 = (int)(n / 4);
    split_kernel<<<(n4 + 255) / 256, 256>>>(x, hi, lo, n4);
}

extern "C" void kernel_launch(void* const* d_in, const int* in_sizes, int n_in,
                              void* d_out, int out_size)
{
    const float* h    = (const float*)d_in[0];
    const float* mask = (const float*)d_in[1];
    const float* wq   = (const float*)d_in[2];
    const float* wk   = (const float*)d_in[3];
    const float* wv   = (const float*)d_in[4];
    const float* wmh  = (const float*)d_in[5];
    const float* g1   = (const float*)d_in[6];
    const float* be1  = (const float*)d_in[7];
    const float* w1   = (const float*)d_in[8];
    const float* b1   = (const float*)d_in[9];
    const float* w2   = (const float*)d_in[10];
    const float* b2   = (const float*)d_in[11];
    const float* g2   = (const float*)d_in[12];
    const float* be2  = (const float*)d_in[13];
    float* out = (float*)d_out;

    float *q, *k, *v, *o, *h2, *a, *hid, *f;
    cudaGetSymbolAddress((void**)&q,   g_q);
    cudaGetSymbolAddress((void**)&k,   g_k);
    cudaGetSymbolAddress((void**)&v,   g_v);
    cudaGetSymbolAddress((void**)&o,   g_o);
    cudaGetSymbolAddress((void**)&h2,  g_h2);
    cudaGetSymbolAddress((void**)&a,   g_a);
    cudaGetSymbolAddress((void**)&hid, g_hid);
    cudaGetSymbolAddress((void**)&f,   g_f);

    __nv_bfloat16 *hbh, *hbl, *obh, *obl, *abh, *abl, *hdh, *hdl;
    __nv_bfloat16 *wqh, *wql, *wkh, *wkl, *wvh, *wvl, *wmh2, *wml, *w1h, *w1l, *w2h, *w2l;
    cudaGetSymbolAddress((void**)&hbh, g_hb_h);  cudaGetSymbolAddress((void**)&hbl, g_hb_l);
    cudaGetSymbolAddress((void**)&obh, g_ob_h);  cudaGetSymbolAddress((void**)&obl, g_ob_l);
    cudaGetSymbolAddress((void**)&abh, g_ab_h);  cudaGetSymbolAddress((void**)&abl, g_ab_l);
    cudaGetSymbolAddress((void**)&hdh, g_hidb_h);cudaGetSymbolAddress((void**)&hdl, g_hidb_l);
    cudaGetSymbolAddress((void**)&wqh, g_wqb_h); cudaGetSymbolAddress((void**)&wql, g_wqb_l);
    cudaGetSymbolAddress((void**)&wkh, g_wkb_h); cudaGetSymbolAddress((void**)&wkl, g_wkb_l);
    cudaGetSymbolAddress((void**)&wvh, g_wvb_h); cudaGetSymbolAddress((void**)&wvl, g_wvb_l);
    cudaGetSymbolAddress((void**)&wmh2,g_wmb_h); cudaGetSymbolAddress((void**)&wml, g_wmb_l);
    cudaGetSymbolAddress((void**)&w1h, g_w1b_h); cudaGetSymbolAddress((void**)&w1l, g_w1b_l);
    cudaGetSymbolAddress((void**)&w2h, g_w2b_h); cudaGetSymbolAddress((void**)&w2l, g_w2b_l);

    const int ATTN_SMEM = 4 * 64 * 68 * (int)sizeof(float);
    cudaFuncSetAttribute(attn_kernel, cudaFuncAttributeMaxDynamicSharedMemorySize, ATTN_SMEM);
    cudaFuncSetAttribute(gemm_mma<0>, cudaFuncAttributeMaxDynamicSharedMemorySize, SMEM_MMA);
    cudaFuncSetAttribute(gemm_mma<1>, cudaFuncAttributeMaxDynamicSharedMemorySize, SMEM_MMA);
    cudaFuncSetAttribute(gemm_mma<2>, cudaFuncAttributeMaxDynamicSharedMemorySize, SMEM_MMA);
    cudaFuncSetAttribute(gemm_mma<3>, cudaFuncAttributeMaxDynamicSharedMemorySize, SMEM_MMA);

    // --- splits of inputs/weights -------------------------------------------
    split(h,   hbh, hbl, (size_t)MTOK * EE);
    split(wq,  wqh, wql, (size_t)EE * EE);
    split(wk,  wkh, wkl, (size_t)EE * EE);
    split(wv,  wvh, wvl, (size_t)EE * EE);
    split(wmh, wmh2, wml, (size_t)EE * EE);
    split(w1,  w1h, w1l, (size_t)HIDD * EE);
    split(w2,  w2h, w2l, (size_t)EE * HIDD);

    dim3 blk(512);
    dim3 gE(EE / TN, MTOK / TM);        // (8, 64)
    dim3 gHid(HIDD / TN, MTOK / TM);    // (32, 64)

    // QKV projections
    gemm_mma<0><<<gE, blk, SMEM_MMA>>>(hbh, hbl, wqh, wql, nullptr, nullptr, q, MTOK, EE, EE);
    gemm_mma<0><<<gE, blk, SMEM_MMA>>>(hbh, hbl, wkh, wkl, nullptr, nullptr, k, MTOK, EE, EE);
    gemm_mma<0><<<gE, blk, SMEM_MMA>>>(hbh, hbl, wvh, wvl, nullptr, nullptr, v, MTOK, EE, EE);

    // fused masked flash attention -> g_o
    attn_kernel<<<dim3(SS / 64, HH, BB), dim3(256), ATTN_SMEM>>>(mask);

    // mh projection + residual
    split(o, obh, obl, (size_t)MTOK * EE);
    gemm_mma<3><<<gE, blk, SMEM_MMA>>>(obh, obl, wmh2, wml, nullptr, h, h2, MTOK, EE, EE);

    // attn_norm
    ln_kernel<<<MTOK, 256>>>(h2, nullptr, nullptr, g1, be1, a, 0);

    // FFN
    split(a, abh, abl, (size_t)MTOK * EE);
    gemm_mma<2><<<gHid, blk, SMEM_MMA>>>(abh, abl, w1h, w1l, b1, nullptr, hid, MTOK, HIDD, EE);
    split(hid, hdh, hdl, (size_t)MTOK * HIDD);
    gemm_mma<1><<<gE, blk, SMEM_MMA>>>(hdh, hdl, w2h, w2l, b2, nullptr, f, MTOK, EE, HIDD);

    // gated residual + ffn_norm
    ln_kernel<<<MTOK, 256>>>(a, f, mask, g2, be2, out, 1);
}

// round 4
// speedup vs baseline: 2.7576x; 1.2529x over previous
#include <cuda_runtime.h>
#include <cuda_bf16.h>
#include <math.h>
#include <stdint.h>

#define BB   8
#define SS   1024
#define EE   1024
#define HH   16
#define DHH  64
#define HIDD 4096
#define MTOK (BB*SS)   // 8192 token rows

// ---------------- fp32 scratch ---------------------------------------------
__device__ float g_h2 [(size_t)MTOK*EE];
__device__ float g_a  [(size_t)MTOK*EE];
__device__ float g_f  [(size_t)MTOK*EE];

// ---------------- bf16 split scratch (hi/lo) --------------------------------
__device__ __nv_bfloat16 g_hb_h [(size_t)MTOK*EE],  g_hb_l [(size_t)MTOK*EE];
__device__ __nv_bfloat16 g_qb_h [(size_t)MTOK*EE],  g_qb_l [(size_t)MTOK*EE];
__device__ __nv_bfloat16 g_kb_h [(size_t)MTOK*EE],  g_kb_l [(size_t)MTOK*EE];
__device__ __nv_bfloat16 g_vb_h [(size_t)MTOK*EE],  g_vb_l [(size_t)MTOK*EE];
__device__ __nv_bfloat16 g_ob_h [(size_t)MTOK*EE],  g_ob_l [(size_t)MTOK*EE];
__device__ __nv_bfloat16 g_ab_h [(size_t)MTOK*EE],  g_ab_l [(size_t)MTOK*EE];
__device__ __nv_bfloat16 g_hidb_h[(size_t)MTOK*HIDD], g_hidb_l[(size_t)MTOK*HIDD];
__device__ __nv_bfloat16 g_wqb_h[(size_t)EE*EE],   g_wqb_l[(size_t)EE*EE];
__device__ __nv_bfloat16 g_wkb_h[(size_t)EE*EE],   g_wkb_l[(size_t)EE*EE];
__device__ __nv_bfloat16 g_wvb_h[(size_t)EE*EE],   g_wvb_l[(size_t)EE*EE];
__device__ __nv_bfloat16 g_wmb_h[(size_t)EE*EE],   g_wmb_l[(size_t)EE*EE];
__device__ __nv_bfloat16 g_w1b_h[(size_t)HIDD*EE], g_w1b_l[(size_t)HIDD*EE];
__device__ __nv_bfloat16 g_w2b_h[(size_t)EE*HIDD], g_w2b_l[(size_t)EE*HIDD];

__device__ __forceinline__ float gelu_exact(float x) {
    return 0.5f * x * (1.0f + erff(x * 0.70710678118654752f));
}

// ============================ PTX helpers (sm_100-safe) =====================
__device__ __forceinline__ uint32_t smem_u32(const void* p) {
    uint32_t a;
    asm("{ .reg .u64 t; cvta.to.shared.u64 t, %1; cvt.u32.u64 %0, t; }"
        : "=r"(a) : "l"(p));
    return a;
}
__device__ __forceinline__ void cp16(uint32_t s, const void* g) {
    asm volatile("cp.async.cg.shared.global [%0], [%1], 16;" :: "r"(s), "l"(g));
}
__device__ __forceinline__ void cp_commit() {
    asm volatile("cp.async.commit_group;" ::: "memory");
}
template<int N>
__device__ __forceinline__ void cp_wait() {
    asm volatile("cp.async.wait_group %0;" :: "n"(N) : "memory");
}
__device__ __forceinline__ void ldsm4(uint32_t& r0, uint32_t& r1,
                                      uint32_t& r2, uint32_t& r3, uint32_t a) {
    asm volatile("ldmatrix.sync.aligned.m8n8.x4.shared.b16 {%0,%1,%2,%3}, [%4];"
                 : "=r"(r0), "=r"(r1), "=r"(r2), "=r"(r3) : "r"(a));
}
__device__ __forceinline__ void ldsm4t(uint32_t& r0, uint32_t& r1,
                                       uint32_t& r2, uint32_t& r3, uint32_t a) {
    asm volatile("ldmatrix.sync.aligned.m8n8.x4.trans.shared.b16 {%0,%1,%2,%3}, [%4];"
                 : "=r"(r0), "=r"(r1), "=r"(r2), "=r"(r3) : "r"(a));
}
__device__ __forceinline__ void mma16816(float* d, const uint32_t* a, const uint32_t* b) {
    asm volatile(
        "mma.sync.aligned.m16n8k16.row.col.f32.bf16.bf16.f32 "
        "{%0,%1,%2,%3}, {%4,%5,%6,%7}, {%8,%9}, {%0,%1,%2,%3};"
        : "+f"(d[0]), "+f"(d[1]), "+f"(d[2]), "+f"(d[3])
        : "r"(a[0]), "r"(a[1]), "r"(a[2]), "r"(a[3]), "r"(b[0]), "r"(b[1]));
}
// fp32 pair -> packed bf16 hi + packed bf16 lo (a in low half, b in high half)
__device__ __forceinline__ void pack_hilo(uint32_t& ph, uint32_t& pl, float a, float b) {
    __nv_bfloat16 ha = __float2bfloat16(a), hb = __float2bfloat16(b);
    float ra = a - __bfloat162float(ha), rb = b - __bfloat162float(hb);
    __nv_bfloat162 vh = __halves2bfloat162(ha, hb);
    __nv_bfloat162 vl = __halves2bfloat162(__float2bfloat16(ra), __float2bfloat16(rb));
    ph = *(uint32_t*)&vh; pl = *(uint32_t*)&vl;
}

// ============================================================================
// split: fp32 x -> bf16 hi + bf16 lo
// ============================================================================
__global__ void __launch_bounds__(256) split_kernel(
    const float* __restrict__ x,
    __nv_bfloat16* __restrict__ hi, __nv_bfloat16* __restrict__ lo, int n4)
{
    int i = blockIdx.x * 256 + threadIdx.x;
    if (i >= n4) return;
    float4 v = ((const float4*)x)[i];
    uint32_t h0, l0, h1, l1;
    pack_hilo(h0, l0, v.x, v.y);
    pack_hilo(h1, l1, v.z, v.w);
    ((uint32_t*)hi)[2*i]   = h0;
    ((uint32_t*)hi)[2*i+1] = h1;
    ((uint32_t*)lo)[2*i]   = l0;
    ((uint32_t*)lo)[2*i+1] = l1;
}

// ============================================================================
// HMMA GEMM: C[M,N] = A[M,K] @ W[N,K]^T  (bf16x3 split, fp32 accumulate)
// CTA 128x128, BK=32, 512 threads. EPI: 0=none,1=+bias,2=+bias,GELU,3=+res
// SOUT: 0 = fp32 C; 1 = bf16 split (Ch, Cl)
// ============================================================================
#define TM 128
#define TN 128
#define BK 32
#define ROWB 80
#define SUBB (128 * ROWB)
#define STAGE_B (4 * SUBB)
#define SMEM_MMA (3 * STAGE_B)

template<int EPI, int SOUT>
__global__ void __launch_bounds__(512, 1) gemm_mma(
    const __nv_bfloat16* __restrict__ Ahi, const __nv_bfloat16* __restrict__ Alo,
    const __nv_bfloat16* __restrict__ Whi, const __nv_bfloat16* __restrict__ Wlo,
    const float* __restrict__ bias, const float* __restrict__ res,
    float* __restrict__ C,
    __nv_bfloat16* __restrict__ Ch, __nv_bfloat16* __restrict__ Cl,
    int M, int N, int K)
{
    extern __shared__ __align__(128) char smem[];
    const uint32_t sb = smem_u32(smem);
    const int tid  = threadIdx.x;
    const int lane = tid & 31;
    const int wid  = tid >> 5;
    const int wm   = wid & 3;
    const int wn   = wid >> 2;
    const int m0   = blockIdx.y * TM;
    const int n0   = blockIdx.x * TN;

    const int lrow = tid >> 2, lc16 = tid & 3;
    const size_t   ga   = (size_t)(m0 + lrow) * K + lc16 * 8;
    const size_t   gw   = (size_t)(n0 + lrow) * K + lc16 * 8;
    const uint32_t soff = lrow * ROWB + lc16 * 16;

    const uint32_t a_row  = wm * 32 + (lane & 15);
    const uint32_t a_coff = (lane >> 4) * 16;
    const uint32_t b_row  = wn * 32 + ((lane >> 4) << 3) + (lane & 7);
    const uint32_t b_coff = ((lane >> 3) & 1) * 16;

    float acc[2][4][4];
#pragma unroll
    for (int mt = 0; mt < 2; mt++)
#pragma unroll
        for (int nt = 0; nt < 4; nt++)
#pragma unroll
            for (int r = 0; r < 4; r++) acc[mt][nt][r] = 0.f;

    const int nst = K / BK;
#pragma unroll
    for (int s = 0; s < 2; s++) {
        const uint32_t b = sb + s * STAGE_B;
        const int k0 = s * BK;
        cp16(b + 0*SUBB + soff, Ahi + ga + k0);
        cp16(b + 1*SUBB + soff, Alo + ga + k0);
        cp16(b + 2*SUBB + soff, Whi + gw + k0);
        cp16(b + 3*SUBB + soff, Wlo + gw + k0);
        cp_commit();
    }

    int sbuf = 0;
    for (int s = 0; s < nst; s++) {
        cp_wait<1>();
        __syncthreads();

        if (s + 2 < nst) {
            const int nb = (sbuf + 2 >= 3) ? sbuf - 1 : sbuf + 2;
            const uint32_t b = sb + nb * STAGE_B;
            const int k0 = (s + 2) * BK;
            cp16(b + 0*SUBB + soff, Ahi + ga + k0);
            cp16(b + 1*SUBB + soff, Alo + ga + k0);
            cp16(b + 2*SUBB + soff, Whi + gw + k0);
            cp16(b + 3*SUBB + soff, Wlo + gw + k0);
            cp_commit();
        }

        const uint32_t bbase = sb + sbuf * STAGE_B;
#pragma unroll
        for (int kk = 0; kk < 2; kk++) {
            uint32_t ah[2][4], al[2][4];
#pragma unroll
            for (int mt = 0; mt < 2; mt++) {
                uint32_t ad = bbase + (a_row + mt * 16) * ROWB + a_coff + kk * 32;
                ldsm4(ah[mt][0], ah[mt][1], ah[mt][2], ah[mt][3], ad);
                ldsm4(al[mt][0], al[mt][1], al[mt][2], al[mt][3], ad + SUBB);
            }
            uint32_t bh[2][4], bl[2][4];
#pragma unroll
            for (int np = 0; np < 2; np++) {
                uint32_t bd = bbase + 2*SUBB + (b_row + np * 16) * ROWB + b_coff + kk * 32;
                ldsm4(bh[np][0], bh[np][1], bh[np][2], bh[np][3], bd);
                ldsm4(bl[np][0], bl[np][1], bl[np][2], bl[np][3], bd + SUBB);
            }
#pragma unroll
            for (int mt = 0; mt < 2; mt++)
#pragma unroll
                for (int nt = 0; nt < 4; nt++) {
                    const uint32_t* Bh = &bh[nt >> 1][(nt & 1) * 2];
                    const uint32_t* Bl = &bl[nt >> 1][(nt & 1) * 2];
                    mma16816(acc[mt][nt], ah[mt], Bh);
                    mma16816(acc[mt][nt], ah[mt], Bl);
                    mma16816(acc[mt][nt], al[mt], Bh);
                }
        }
        __syncthreads();
        sbuf = (sbuf + 1 >= 3) ? 0 : sbuf + 1;
    }

#pragma unroll
    for (int mt = 0; mt < 2; mt++) {
        const int rowA = m0 + wm * 32 + mt * 16 + (lane >> 2);
#pragma unroll
        for (int nt = 0; nt < 4; nt++) {
            const int col = n0 + wn * 32 + nt * 8 + (lane & 3) * 2;
            float b0 = 0.f, b1 = 0.f;
            if (EPI == 1 || EPI == 2) { b0 = bias[col]; b1 = bias[col + 1]; }
#pragma unroll
            for (int half = 0; half < 2; half++) {
                const int row = rowA + half * 8;
                float v0 = acc[mt][nt][half * 2 + 0];
                float v1 = acc[mt][nt][half * 2 + 1];
                if (EPI == 1 || EPI == 2) { v0 += b0; v1 += b1; }
                if (EPI == 2) { v0 = gelu_exact(v0); v1 = gelu_exact(v1); }
                const size_t go = (size_t)row * N + col;
                if (EPI == 3) {
                    float2 r2 = *(const float2*)&res[go];
                    v0 += r2.x; v1 += r2.y;
                }
                if (SOUT) {
                    uint32_t ph, pl;
                    pack_hilo(ph, pl, v0, v1);
                    *(uint32_t*)&Ch[go] = ph;
                    *(uint32_t*)&Cl[go] = pl;
                } else {
                    *(float2*)&C[go] = make_float2(v0, v1);
                }
            }
        }
    }
}

// ============================================================================
// HMMA FlashAttention: CTA = (qtile 64, head, batch), 128 threads (4 warps).
// bf16x3 for QK^T and P.V, fp32 online softmax, faithful masked renorm.
// Writes o directly as split bf16.
// ============================================================================
#define AT_ROW 144                       // bytes per smem row (64 bf16 + pad)
#define AT_SUB (64 * AT_ROW)             // 9216 B per sub-tile
#define AT_STAGE (4 * AT_SUB)            // KH | KL | VH | VL
#define SMEM_ATT (2*AT_SUB + 2*AT_STAGE) // Q(hi/lo) + 2 KV stages = 92160 B

__device__ __forceinline__ void at_ldtile(
    uint32_t dsth, uint32_t dstl,
    const __nv_bfloat16* __restrict__ gh, const __nv_bfloat16* __restrict__ gl,
    size_t row0, int col0, int tid)
{
#pragma unroll
    for (int i = 0; i < 4; i++) {
        int idx = tid + i * 128;
        int r = idx >> 3, c = idx & 7;
        uint32_t so = r * AT_ROW + c * 16;
        size_t g = (row0 + r) * EE + col0 + c * 8;
        cp16(dsth + so, gh + g);
        cp16(dstl + so, gl + g);
    }
}

__global__ void __launch_bounds__(128, 1) attn_mma(
    const float* __restrict__ mask,
    const __nv_bfloat16* __restrict__ qh, const __nv_bfloat16* __restrict__ ql,
    const __nv_bfloat16* __restrict__ kh, const __nv_bfloat16* __restrict__ kl,
    const __nv_bfloat16* __restrict__ vh, const __nv_bfloat16* __restrict__ vl,
    __nv_bfloat16* __restrict__ oh, __nv_bfloat16* __restrict__ ol)
{
    extern __shared__ __align__(128) char smn[];
    const uint32_t sb = smem_u32(smn);
    const int qt = blockIdx.x, hd = blockIdx.y, b = blockIdx.z;
    const int tid = threadIdx.x;
    const int lane = tid & 31;
    const int w = tid >> 5;
    const int col0 = hd * 64;
    const size_t qrow0 = (size_t)b * SS + (size_t)qt * 64;

    const uint32_t QH = sb, QL = sb + AT_SUB;
    const uint32_t ST0 = sb + 2 * AT_SUB;

    // G0: Q + KV(0)
    at_ldtile(QH, QL, qh, ql, qrow0, col0, tid);
    {
        size_t kr = (size_t)b * SS;
        at_ldtile(ST0,            ST0 + AT_SUB,   kh, kl, kr, col0, tid);
        at_ldtile(ST0 + 2*AT_SUB, ST0 + 3*AT_SUB, vh, vl, kr, col0, tid);
    }
    cp_commit();
    // G1: KV(1)
    {
        size_t kr = (size_t)b * SS + 64;
        uint32_t s1 = ST0 + AT_STAGE;
        at_ldtile(s1,            s1 + AT_SUB,   kh, kl, kr, col0, tid);
        at_ldtile(s1 + 2*AT_SUB, s1 + 3*AT_SUB, vh, vl, kr, col0, tid);
    }
    cp_commit();
    cp_wait<1>();
    __syncthreads();

    // Q fragments (persist in regs): 4 k16 chunks
    uint32_t fqh[4][4], fql[4][4];
    {
        uint32_t qa = QH + (w * 16 + (lane & 15)) * AT_ROW + (lane >> 4) * 16;
#pragma unroll
        for (int c = 0; c < 4; c++) {
            ldsm4(fqh[c][0], fqh[c][1], fqh[c][2], fqh[c][3], qa + c * 32);
            ldsm4(fql[c][0], fql[c][1], fql[c][2], fql[c][3], qa + c * 32 + AT_SUB);
        }
    }

    float oacc[8][4];
#pragma unroll
    for (int t = 0; t < 8; t++)
#pragma unroll
        for (int r = 0; r < 4; r++) oacc[t][r] = 0.f;
    float rmax0 = -1e30f, rmax1 = -1e30f, rsum0 = 0.f, rsum1 = 0.f;

    // mask row pointers for this thread's two rows
    const float* mrow0 = mask + ((size_t)b * SS + qt * 64 + w * 16 + (lane >> 2)) * SS
                              + (lane & 3) * 2;
    const float* mrow1 = mrow0 + 8 * SS;

    for (int kt = 0; kt < 16; kt++) {
        if (kt > 0) {
            if (kt + 1 < 16) {
                size_t kr = (size_t)b * SS + (size_t)(kt + 1) * 64;
                uint32_t s1 = ST0 + ((kt + 1) & 1) * AT_STAGE;
                at_ldtile(s1,            s1 + AT_SUB,   kh, kl, kr, col0, tid);
                at_ldtile(s1 + 2*AT_SUB, s1 + 3*AT_SUB, vh, vl, kr, col0, tid);
                cp_commit();
                cp_wait<1>();
            } else {
                cp_wait<0>();
            }
            __syncthreads();
        }

        const uint32_t kb = ST0 + (kt & 1) * AT_STAGE;
        const uint32_t vb = kb + 2 * AT_SUB;

        // ---- scores = Q K^T (bf16x3) ----
        float sacc[8][4];
#pragma unroll
        for (int t = 0; t < 8; t++)
#pragma unroll
            for (int r = 0; r < 4; r++) sacc[t][r] = 0.f;

#pragma unroll
        for (int c = 0; c < 4; c++) {
#pragma unroll
            for (int np = 0; np < 4; np++) {
                uint32_t ka = kb + (np * 16 + ((lane >> 4) << 3) + (lane & 7)) * AT_ROW
                            + ((lane >> 3) & 1) * 16 + c * 32;
                uint32_t bh[4], bl[4];
                ldsm4(bh[0], bh[1], bh[2], bh[3], ka);
                ldsm4(bl[0], bl[1], bl[2], bl[3], ka + AT_SUB);
                mma16816(sacc[2*np],   fqh[c], &bh[0]);
                mma16816(sacc[2*np],   fqh[c], &bl[0]);
                mma16816(sacc[2*np],   fql[c], &bh[0]);
                mma16816(sacc[2*np+1], fqh[c], &bh[2]);
                mma16816(sacc[2*np+1], fqh[c], &bl[2]);
                mma16816(sacc[2*np+1], fql[c], &bh[2]);
            }
        }

        // ---- online masked softmax ----
        const float* mk0 = mrow0 + kt * 64;
        const float* mk1 = mrow1 + kt * 64;
        float tmax0 = -1e30f, tmax1 = -1e30f;
#pragma unroll
        for (int t = 0; t < 8; t++) {
            float2 ma = *(const float2*)(mk0 + t * 8);
            float2 mb = *(const float2*)(mk1 + t * 8);
            sacc[t][0] = sacc[t][0] * 0.125f * ma.x;
            sacc[t][1] = sacc[t][1] * 0.125f * ma.y;
            sacc[t][2] = sacc[t][2] * 0.125f * mb.x;
            sacc[t][3] = sacc[t][3] * 0.125f * mb.y;
            tmax0 = fmaxf(tmax0, fmaxf(sacc[t][0], sacc[t][1]));
            tmax1 = fmaxf(tmax1, fmaxf(sacc[t][2], sacc[t][3]));
        }
        tmax0 = fmaxf(tmax0, __shfl_xor_sync(0xffffffffu, tmax0, 1));
        tmax0 = fmaxf(tmax0, __shfl_xor_sync(0xffffffffu, tmax0, 2));
        tmax1 = fmaxf(tmax1, __shfl_xor_sync(0xffffffffu, tmax1, 1));
        tmax1 = fmaxf(tmax1, __shfl_xor_sync(0xffffffffu, tmax1, 2));
        float nmax0 = fmaxf(rmax0, tmax0), nmax1 = fmaxf(rmax1, tmax1);
        float corr0 = __expf(rmax0 - nmax0), corr1 = __expf(rmax1 - nmax1);
        rmax0 = nmax0; rmax1 = nmax1;

        float ts0 = 0.f, ts1 = 0.f;
#pragma unroll
        for (int t = 0; t < 8; t++) {
            float2 ma = *(const float2*)(mk0 + t * 8);
            float2 mb = *(const float2*)(mk1 + t * 8);
            float e0 = __expf(sacc[t][0] - nmax0) * ma.x;
            float e1 = __expf(sacc[t][1] - nmax0) * ma.y;
            float e2 = __expf(sacc[t][2] - nmax1) * mb.x;
            float e3 = __expf(sacc[t][3] - nmax1) * mb.y;
            ts0 += e0 + e1; ts1 += e2 + e3;
            sacc[t][0] = e0; sacc[t][1] = e1; sacc[t][2] = e2; sacc[t][3] = e3;
        }
        ts0 += __shfl_xor_sync(0xffffffffu, ts0, 1);
        ts0 += __shfl_xor_sync(0xffffffffu, ts0, 2);
        ts1 += __shfl_xor_sync(0xffffffffu, ts1, 1);
        ts1 += __shfl_xor_sync(0xffffffffu, ts1, 2);
        rsum0 = rsum0 * corr0 + ts0;
        rsum1 = rsum1 * corr1 + ts1;
#pragma unroll
        for (int t = 0; t < 8; t++) {
            oacc[t][0] *= corr0; oacc[t][1] *= corr0;
            oacc[t][2] *= corr1; oacc[t][3] *= corr1;
        }

        // ---- O += P V (bf16x3, P from accumulator regs) ----
#pragma unroll
        for (int c = 0; c < 4; c++) {
            uint32_t pah[4], pal[4];
            pack_hilo(pah[0], pal[0], sacc[2*c][0],   sacc[2*c][1]);
            pack_hilo(pah[1], pal[1], sacc[2*c][2],   sacc[2*c][3]);
            pack_hilo(pah[2], pal[2], sacc[2*c+1][0], sacc[2*c+1][1]);
            pack_hilo(pah[3], pal[3], sacc[2*c+1][2], sacc[2*c+1][3]);
#pragma unroll
            for (int nd = 0; nd < 4; nd++) {
                uint32_t va = vb + (c * 16 + ((lane >> 3) & 1) * 8 + (lane & 7)) * AT_ROW
                            + nd * 32 + (lane >> 4) * 16;
                uint32_t wh[4], wl[4];
                ldsm4t(wh[0], wh[1], wh[2], wh[3], va);
                ldsm4t(wl[0], wl[1], wl[2], wl[3], va + AT_SUB);
                mma16816(oacc[2*nd],   pah, &wh[0]);
                mma16816(oacc[2*nd],   pah, &wl[0]);
                mma16816(oacc[2*nd],   pal, &wh[0]);
                mma16816(oacc[2*nd+1], pah, &wh[2]);
                mma16816(oacc[2*nd+1], pah, &wl[2]);
                mma16816(oacc[2*nd+1], pal, &wh[2]);
            }
        }
        __syncthreads();
    }

    // ---- epilogue: normalize + split bf16 store ----
    const float inv0 = 1.0f / (rsum0 + 1e-20f);
    const float inv1 = 1.0f / (rsum1 + 1e-20f);
    const size_t r0g = qrow0 + w * 16 + (lane >> 2);
    const size_t r1g = r0g + 8;
#pragma unroll
    for (int t = 0; t < 8; t++) {
        const int col = col0 + t * 8 + (lane & 3) * 2;
        uint32_t ph, pl;
        pack_hilo(ph, pl, oacc[t][0] * inv0, oacc[t][1] * inv0);
        *(uint32_t*)&oh[r0g * EE + col] = ph;
        *(uint32_t*)&ol[r0g * EE + col] = pl;
        pack_hilo(ph, pl, oacc[t][2] * inv1, oacc[t][3] * inv1);
        *(uint32_t*)&oh[r1g * EE + col] = ph;
        *(uint32_t*)&ol[r1g * EE + col] = pl;
    }
}

// ============================================================================
// LayerNorm over E=1024, optional gated-residual input and split bf16 output.
// ============================================================================
__global__ void __launch_bounds__(256) ln_kernel(
    const float* __restrict__ x, const float* __restrict__ f,
    const float* __restrict__ mask, const float* __restrict__ gamma,
    const float* __restrict__ beta, float* __restrict__ out,
    __nv_bfloat16* __restrict__ outh, __nv_bfloat16* __restrict__ outl, int useF)
{
    const int row = blockIdx.x;
    const int tid = threadIdx.x;

    float4 v4 = *(const float4*)&x[(size_t)row * EE + tid * 4];
    float v[4] = {v4.x, v4.y, v4.z, v4.w};

    if (useF) {
        const int b = row / SS, s = row % SS;
        const float gate = mask[((size_t)b * SS + (SS - 1)) * SS + s];
        float4 f4 = *(const float4*)&f[(size_t)row * EE + tid * 4];
        v[0] += f4.x * gate; v[1] += f4.y * gate;
        v[2] += f4.z * gate; v[3] += f4.w * gate;
    }

    float s1 = v[0] + v[1] + v[2] + v[3];
    float s2 = v[0]*v[0] + v[1]*v[1] + v[2]*v[2] + v[3]*v[3];
#pragma unroll
    for (int ofs = 16; ofs >= 1; ofs >>= 1) {
        s1 += __shfl_xor_sync(0xffffffffu, s1, ofs);
        s2 += __shfl_xor_sync(0xffffffffu, s2, ofs);
    }
    __shared__ float red1[8], red2[8];
    if ((tid & 31) == 0) { red1[tid >> 5] = s1; red2[tid >> 5] = s2; }
    __syncthreads();
    float t1 = 0.f, t2 = 0.f;
#pragma unroll
    for (int wv = 0; wv < 8; wv++) { t1 += red1[wv]; t2 += red2[wv]; }

    const float mean = t1 * (1.0f / EE);
    const float var  = t2 * (1.0f / EE) - mean * mean;
    const float inv  = rsqrtf(var + 1e-5f);

    float4 g4 = *(const float4*)&gamma[tid * 4];
    float4 b4 = *(const float4*)&beta[tid * 4];
    float o0 = (v[0] - mean) * inv * g4.x + b4.x;
    float o1 = (v[1] - mean) * inv * g4.y + b4.y;
    float o2 = (v[2] - mean) * inv * g4.z + b4.z;
    float o3 = (v[3] - mean) * inv * g4.w + b4.w;
    if (out)
        *(float4*)&out[(size_t)row * EE + tid * 4] = make_float4(o0, o1, o2, o3);
    if (outh) {
        uint32_t h0, l0, h1, l1;
        pack_hilo(h0, l0, o0, o1);
        pack_hilo(h1, l1, o2, o3);
        const size_t go = (size_t)row * EE + tid * 4;
        *(uint32_t*)&outh[go]     = h0;
        *(uint32_t*)&outh[go + 2] = h1;
        *(uint32_t*)&outl[go]     = l0;
        *(uint32_t*)&outl[go + 2] = l1;
    }
}

// ============================================================================
static inline void split(const float* x, __nv_bfloat16* hi, __nv_bfloat16* lo, size_t n)
{
    int n4 = (int)(n / 4);
    split_kernel<<<(n4 + 255) / 256, 256>>>(x, hi, lo, n4);
}

extern "C" void kernel_launch(void* const* d_in, const int* in_sizes, int n_in,
                              void* d_out, int out_size)
{
    const float* h    = (const float*)d_in[0];
    const float* mask = (const float*)d_in[1];
    const float* wq   = (const float*)d_in[2];
    const float* wk   = (const float*)d_in[3];
    const float* wv   = (const float*)d_in[4];
    const float* wmh  = (const float*)d_in[5];
    const float* g1   = (const float*)d_in[6];
    const float* be1  = (const float*)d_in[7];
    const float* w1   = (const float*)d_in[8];
    const float* b1   = (const float*)d_in[9];
    const float* w2   = (const float*)d_in[10];
    const float* b2   = (const float*)d_in[11];
    const float* g2   = (const float*)d_in[12];
    const float* be2  = (const float*)d_in[13];
    float* out = (float*)d_out;

    float *h2, *a, *f;
    cudaGetSymbolAddress((void**)&h2,  g_h2);
    cudaGetSymbolAddress((void**)&a,   g_a);
    cudaGetSymbolAddress((void**)&f,   g_f);

    __nv_bfloat16 *hbh, *hbl, *qbh, *qbl, *kbh, *kbl, *vbh, *vbl, *obh, *obl;
    __nv_bfloat16 *abh, *abl, *hdh, *hdl;
    __nv_bfloat16 *wqh, *wql, *wkh, *wkl, *wvh, *wvl, *wmh2, *wml, *w1h, *w1l, *w2h, *w2l;
    cudaGetSymbolAddress((void**)&hbh, g_hb_h);  cudaGetSymbolAddress((void**)&hbl, g_hb_l);
    cudaGetSymbolAddress((void**)&qbh, g_qb_h);  cudaGetSymbolAddress((void**)&qbl, g_qb_l);
    cudaGetSymbolAddress((void**)&kbh, g_kb_h);  cudaGetSymbolAddress((void**)&kbl, g_kb_l);
    cudaGetSymbolAddress((void**)&vbh, g_vb_h);  cudaGetSymbolAddress((void**)&vbl, g_vb_l);
    cudaGetSymbolAddress((void**)&obh, g_ob_h);  cudaGetSymbolAddress((void**)&obl, g_ob_l);
    cudaGetSymbolAddress((void**)&abh, g_ab_h);  cudaGetSymbolAddress((void**)&abl, g_ab_l);
    cudaGetSymbolAddress((void**)&hdh, g_hidb_h);cudaGetSymbolAddress((void**)&hdl, g_hidb_l);
    cudaGetSymbolAddress((void**)&wqh, g_wqb_h); cudaGetSymbolAddress((void**)&wql, g_wqb_l);
    cudaGetSymbolAddress((void**)&wkh, g_wkb_h); cudaGetSymbolAddress((void**)&wkl, g_wkb_l);
    cudaGetSymbolAddress((void**)&wvh, g_wvb_h); cudaGetSymbolAddress((void**)&wvl, g_wvb_l);
    cudaGetSymbolAddress((void**)&wmh2,g_wmb_h); cudaGetSymbolAddress((void**)&wml, g_wmb_l);
    cudaGetSymbolAddress((void**)&w1h, g_w1b_h); cudaGetSymbolAddress((void**)&w1l, g_w1b_l);
    cudaGetSymbolAddress((void**)&w2h, g_w2b_h); cudaGetSymbolAddress((void**)&w2l, g_w2b_l);

    cudaFuncSetAttribute(attn_mma, cudaFuncAttributeMaxDynamicSharedMemorySize, SMEM_ATT);
    cudaFuncSetAttribute(gemm_mma<0,1>, cudaFuncAttributeMaxDynamicSharedMemorySize, SMEM_MMA);
    cudaFuncSetAttribute(gemm_mma<3,0>, cudaFuncAttributeMaxDynamicSharedMemorySize, SMEM_MMA);
    cudaFuncSetAttribute(gemm_mma<2,1>, cudaFuncAttributeMaxDynamicSharedMemorySize, SMEM_MMA);
    cudaFuncSetAttribute(gemm_mma<1,0>, cudaFuncAttributeMaxDynamicSharedMemorySize, SMEM_MMA);

    // splits (inputs + weights only)
    split(h,   hbh, hbl, (size_t)MTOK * EE);
    split(wq,  wqh, wql, (size_t)EE * EE);
    split(wk,  wkh, wkl, (size_t)EE * EE);
    split(wv,  wvh, wvl, (size_t)EE * EE);
    split(wmh, wmh2, wml, (size_t)EE * EE);
    split(w1,  w1h, w1l, (size_t)HIDD * EE);
    split(w2,  w2h, w2l, (size_t)EE * HIDD);

    dim3 blk(512);
    dim3 gE(EE / TN, MTOK / TM);
    dim3 gHid(HIDD / TN, MTOK / TM);

    // QKV projections -> split bf16 outputs
    gemm_mma<0,1><<<gE, blk, SMEM_MMA>>>(hbh, hbl, wqh, wql, nullptr, nullptr,
                                         nullptr, qbh, qbl, MTOK, EE, EE);
    gemm_mma<0,1><<<gE, blk, SMEM_MMA>>>(hbh, hbl, wkh, wkl, nullptr, nullptr,
                                         nullptr, kbh, kbl, MTOK, EE, EE);
    gemm_mma<0,1><<<gE, blk, SMEM_MMA>>>(hbh, hbl, wvh, wvl, nullptr, nullptr,
                                         nullptr, vbh, vbl, MTOK, EE, EE);

    // fused masked flash attention -> o (split bf16)
    attn_mma<<<dim3(SS / 64, HH, BB), dim3(128), SMEM_ATT>>>(
        mask, qbh, qbl, kbh, kbl, vbh, vbl, obh, obl);

    // mh projection + residual -> h2 (fp32)
    gemm_mma<3,0><<<gE, blk, SMEM_MMA>>>(obh, obl, wmh2, wml, nullptr, h,
                                         h2, nullptr, nullptr, MTOK, EE, EE);

    // attn_norm -> a (fp32) + split bf16
    ln_kernel<<<MTOK, 256>>>(h2, nullptr, nullptr, g1, be1, a, abh, abl, 0);

    // FFN1 (+bias, GELU) -> hid split bf16
    gemm_mma<2,1><<<gHid, blk, SMEM_MMA>>>(abh, abl, w1h, w1l, b1, nullptr,
                                           nullptr, hdh, hdl, MTOK, HIDD, EE);
    // FFN2 (+bias) -> f (fp32)
    gemm_mma<1,0><<<gE, blk, SMEM_MMA>>>(hdh, hdl, w2h, w2l, b2, nullptr,
                                         f, nullptr, nullptr, MTOK, EE, HIDD);

    // gated residual + ffn_norm -> out
    ln_kernel<<<MTOK, 256>>>(a, f, mask, g2, be2, out, nullptr, nullptr, 1);
}

// round 5
// speedup vs baseline: 3.8025x; 1.3789x over previous
#include <cuda_runtime.h>
#include <cuda_bf16.h>
#include <cuda_fp16.h>
#include <math.h>
#include <stdint.h>

#define BB   8
#define SS   1024
#define EE   1024
#define HH   16
#define DHH  64
#define HIDD 4096
#define MTOK (BB*SS)   // 8192 token rows

// ---------------- fp32 scratch ---------------------------------------------
__device__ float g_h2 [(size_t)MTOK*EE];
__device__ float g_a  [(size_t)MTOK*EE];
__device__ float g_f  [(size_t)MTOK*EE];

// ---------------- fp16 activation splits (hi/lo) ----------------------------
__device__ __half g_hh [(size_t)MTOK*EE],  g_hl [(size_t)MTOK*EE];
__device__ __half g_oh [(size_t)MTOK*EE],  g_ol [(size_t)MTOK*EE];
__device__ __half g_ah [(size_t)MTOK*EE],  g_al [(size_t)MTOK*EE];
__device__ __half g_hidh[(size_t)MTOK*HIDD], g_hidl[(size_t)MTOK*HIDD];

// ---------------- fp16 weights (hi only) ------------------------------------
__device__ __half g_w16q[(size_t)EE*EE];
__device__ __half g_w16k[(size_t)EE*EE];
__device__ __half g_w16v[(size_t)EE*EE];
__device__ __half g_w16m[(size_t)EE*EE];
__device__ __half g_w16a[(size_t)HIDD*EE];
__device__ __half g_w16b[(size_t)EE*HIDD];

// ---------------- bf16 q/k/v splits (attention uses bf16x3) -----------------
__device__ __nv_bfloat16 g_qbh[(size_t)MTOK*EE], g_qbl[(size_t)MTOK*EE];
__device__ __nv_bfloat16 g_kbh[(size_t)MTOK*EE], g_kbl[(size_t)MTOK*EE];
__device__ __nv_bfloat16 g_vbh[(size_t)MTOK*EE], g_vbl[(size_t)MTOK*EE];

__device__ __forceinline__ float gelu_exact(float x) {
    return 0.5f * x * (1.0f + erff(x * 0.70710678118654752f));
}

// ============================ PTX helpers (sm_100-safe) =====================
__device__ __forceinline__ uint32_t smem_u32(const void* p) {
    uint32_t a;
    asm("{ .reg .u64 t; cvta.to.shared.u64 t, %1; cvt.u32.u64 %0, t; }"
        : "=r"(a) : "l"(p));
    return a;
}
__device__ __forceinline__ void cp16(uint32_t s, const void* g) {
    asm volatile("cp.async.cg.shared.global [%0], [%1], 16;" :: "r"(s), "l"(g));
}
__device__ __forceinline__ void cp_commit() {
    asm volatile("cp.async.commit_group;" ::: "memory");
}
template<int N>
__device__ __forceinline__ void cp_wait() {
    asm volatile("cp.async.wait_group %0;" :: "n"(N) : "memory");
}
__device__ __forceinline__ void ldsm4(uint32_t& r0, uint32_t& r1,
                                      uint32_t& r2, uint32_t& r3, uint32_t a) {
    asm volatile("ldmatrix.sync.aligned.m8n8.x4.shared.b16 {%0,%1,%2,%3}, [%4];"
                 : "=r"(r0), "=r"(r1), "=r"(r2), "=r"(r3) : "r"(a));
}
__device__ __forceinline__ void ldsm4t(uint32_t& r0, uint32_t& r1,
                                       uint32_t& r2, uint32_t& r3, uint32_t a) {
    asm volatile("ldmatrix.sync.aligned.m8n8.x4.trans.shared.b16 {%0,%1,%2,%3}, [%4];"
                 : "=r"(r0), "=r"(r1), "=r"(r2), "=r"(r3) : "r"(a));
}
__device__ __forceinline__ void mma_bf16(float* d, const uint32_t* a, const uint32_t* b) {
    asm volatile(
        "mma.sync.aligned.m16n8k16.row.col.f32.bf16.bf16.f32 "
        "{%0,%1,%2,%3}, {%4,%5,%6,%7}, {%8,%9}, {%0,%1,%2,%3};"
        : "+f"(d[0]), "+f"(d[1]), "+f"(d[2]), "+f"(d[3])
        : "r"(a[0]), "r"(a[1]), "r"(a[2]), "r"(a[3]), "r"(b[0]), "r"(b[1]));
}
__device__ __forceinline__ void mma_f16(float* d, const uint32_t* a, const uint32_t* b) {
    asm volatile(
        "mma.sync.aligned.m16n8k16.row.col.f32.f16.f16.f32 "
        "{%0,%1,%2,%3}, {%4,%5,%6,%7}, {%8,%9}, {%0,%1,%2,%3};"
        : "+f"(d[0]), "+f"(d[1]), "+f"(d[2]), "+f"(d[3])
        : "r"(a[0]), "r"(a[1]), "r"(a[2]), "r"(a[3]), "r"(b[0]), "r"(b[1]));
}
// fp32 pair -> packed bf16 hi + lo
__device__ __forceinline__ void pack_hilo_b(uint32_t& ph, uint32_t& pl, float a, float b) {
    __nv_bfloat16 ha = __float2bfloat16(a), hb = __float2bfloat16(b);
    float ra = a - __bfloat162float(ha), rb = b - __bfloat162float(hb);
    __nv_bfloat162 vh = __halves2bfloat162(ha, hb);
    __nv_bfloat162 vl = __halves2bfloat162(__float2bfloat16(ra), __float2bfloat16(rb));
    ph = *(uint32_t*)&vh; pl = *(uint32_t*)&vl;
}
// fp32 pair -> packed fp16 hi + lo
__device__ __forceinline__ void pack_hilo_h(uint32_t& ph, uint32_t& pl, float a, float b) {
    __half ha = __float2half_rn(a), hb = __float2half_rn(b);
    float ra = a - __half2float(ha), rb = b - __half2float(hb);
    __half2 vh = __halves2half2(ha, hb);
    __half2 vl = __halves2half2(__float2half_rn(ra), __float2half_rn(rb));
    ph = *(uint32_t*)&vh; pl = *(uint32_t*)&vl;
}

// ============================================================================
// split: fp32 -> fp16 hi + lo;  cvt: fp32 -> fp16 (round)
// ============================================================================
__global__ void __launch_bounds__(256) split16_kernel(
    const float* __restrict__ x, __half* __restrict__ hi, __half* __restrict__ lo, int n4)
{
    int i = blockIdx.x * 256 + threadIdx.x;
    if (i >= n4) return;
    float4 v = ((const float4*)x)[i];
    uint32_t h0, l0, h1, l1;
    pack_hilo_h(h0, l0, v.x, v.y);
    pack_hilo_h(h1, l1, v.z, v.w);
    ((uint32_t*)hi)[2*i]   = h0;
    ((uint32_t*)hi)[2*i+1] = h1;
    ((uint32_t*)lo)[2*i]   = l0;
    ((uint32_t*)lo)[2*i+1] = l1;
}
__global__ void __launch_bounds__(256) cvt16_kernel(
    const float* __restrict__ x, __half* __restrict__ y, int n4)
{
    int i = blockIdx.x * 256 + threadIdx.x;
    if (i >= n4) return;
    float4 v = ((const float4*)x)[i];
    __half2 a = __halves2half2(__float2half_rn(v.x), __float2half_rn(v.y));
    __half2 b = __halves2half2(__float2half_rn(v.z), __float2half_rn(v.w));
    ((__half2*)y)[2*i]   = a;
    ((__half2*)y)[2*i+1] = b;
}

// ============================================================================
// fp16x2 GEMM core: C[M,N] = (Ah+Al)[M,K] @ Wh[N,K]^T, fp32 accumulate.
// CTA 128x256, BK=32, 512 threads (16 warps 4x4, warp tile 32x64), 3 stages.
// ============================================================================
#define TM 128
#define TN 256
#define BK 32
#define ROWB 80
#define A_SUB (128 * ROWB)          // 10240 B
#define W_SUB (256 * ROWB)          // 20480 B
#define STG   (2 * A_SUB + W_SUB)   // 40960 B: Ah | Al | Wh
#define SMEM_MMA (3 * STG)          // 122880 B

__device__ __forceinline__ void hgemm_core(
    float acc[2][8][4],
    const __half* __restrict__ Ah, const __half* __restrict__ Al,
    const __half* __restrict__ Wh,
    int m0, int n0, int K, uint32_t sb)
{
    const int tid  = threadIdx.x;
    const int lane = tid & 31;
    const int wid  = tid >> 5;
    const int wm   = wid & 3;
    const int wn   = wid >> 2;

    const int lr = tid >> 2, lc = tid & 3;
    const size_t   ga   = (size_t)(m0 + lr) * K + lc * 8;
    const uint32_t aso  = lr * ROWB + lc * 16;
    const size_t   gw0  = (size_t)(n0 + lr) * K + lc * 8;
    const size_t   gw1  = gw0 + (size_t)128 * K;
    const uint32_t wso0 = lr * ROWB + lc * 16;
    const uint32_t wso1 = wso0 + 128 * ROWB;

    const uint32_t a_row  = wm * 32 + (lane & 15);
    const uint32_t a_coff = (lane >> 4) * 16;
    const uint32_t b_row  = wn * 64 + ((lane >> 4) << 3) + (lane & 7);
    const uint32_t b_coff = ((lane >> 3) & 1) * 16;

#pragma unroll
    for (int mt = 0; mt < 2; mt++)
#pragma unroll
        for (int nt = 0; nt < 8; nt++)
#pragma unroll
            for (int r = 0; r < 4; r++) acc[mt][nt][r] = 0.f;

    const int nst = K / BK;
#pragma unroll
    for (int s = 0; s < 2; s++) {
        const uint32_t b = sb + s * STG;
        const int k0 = s * BK;
        cp16(b + aso,             Ah + ga  + k0);
        cp16(b + A_SUB + aso,     Al + ga  + k0);
        cp16(b + 2*A_SUB + wso0,  Wh + gw0 + k0);
        cp16(b + 2*A_SUB + wso1,  Wh + gw1 + k0);
        cp_commit();
    }

    int sbuf = 0;
    for (int s = 0; s < nst; s++) {
        cp_wait<1>();
        __syncthreads();

        if (s + 2 < nst) {
            const int nb = (sbuf + 2 >= 3) ? sbuf - 1 : sbuf + 2;
            const uint32_t b = sb + nb * STG;
            const int k0 = (s + 2) * BK;
            cp16(b + aso,            Ah + ga  + k0);
            cp16(b + A_SUB + aso,    Al + ga  + k0);
            cp16(b + 2*A_SUB + wso0, Wh + gw0 + k0);
            cp16(b + 2*A_SUB + wso1, Wh + gw1 + k0);
            cp_commit();
        }

        const uint32_t bbase = sb + sbuf * STG;
#pragma unroll
        for (int kk = 0; kk < 2; kk++) {
            uint32_t ah[2][4], al[2][4];
#pragma unroll
            for (int mt = 0; mt < 2; mt++) {
                uint32_t ad = bbase + (a_row + mt * 16) * ROWB + a_coff + kk * 32;
                ldsm4(ah[mt][0], ah[mt][1], ah[mt][2], ah[mt][3], ad);
                ldsm4(al[mt][0], al[mt][1], al[mt][2], al[mt][3], ad + A_SUB);
            }
            uint32_t bh[4][4];
#pragma unroll
            for (int np = 0; np < 4; np++) {
                uint32_t bd = bbase + 2*A_SUB + (b_row + np * 16) * ROWB + b_coff + kk * 32;
                ldsm4(bh[np][0], bh[np][1], bh[np][2], bh[np][3], bd);
            }
#pragma unroll
            for (int mt = 0; mt < 2; mt++)
#pragma unroll
                for (int nt = 0; nt < 8; nt++) {
                    const uint32_t* B = &bh[nt >> 1][(nt & 1) * 2];
                    mma_f16(acc[mt][nt], ah[mt], B);
                    mma_f16(acc[mt][nt], al[mt], B);
                }
        }
        __syncthreads();
        sbuf = (sbuf + 1 >= 3) ? 0 : sbuf + 1;
    }
}

// EPI: 0=none,1=+bias,2=+bias+GELU,3=+res ; SOUT: 0=fp32, 1=bf16 split, 2=fp16 split
template<int EPI, int SOUT>
__device__ __forceinline__ void hgemm_epi(
    float acc[2][8][4], const float* __restrict__ bias, const float* __restrict__ res,
    float* __restrict__ C,
    __nv_bfloat16* __restrict__ Cbh, __nv_bfloat16* __restrict__ Cbl,
    __half* __restrict__ Chh, __half* __restrict__ Chl,
    int m0, int n0, int N)
{
    const int lane = threadIdx.x & 31;
    const int wid  = threadIdx.x >> 5;
    const int wm   = wid & 3, wn = wid >> 2;
#pragma unroll
    for (int mt = 0; mt < 2; mt++) {
        const int rowA = m0 + wm * 32 + mt * 16 + (lane >> 2);
#pragma unroll
        for (int nt = 0; nt < 8; nt++) {
            const int col = n0 + wn * 64 + nt * 8 + (lane & 3) * 2;
            float b0 = 0.f, b1 = 0.f;
            if (EPI == 1 || EPI == 2) { b0 = bias[col]; b1 = bias[col + 1]; }
#pragma unroll
            for (int hf = 0; hf < 2; hf++) {
                const int row = rowA + hf * 8;
                float v0 = acc[mt][nt][hf * 2 + 0];
                float v1 = acc[mt][nt][hf * 2 + 1];
                if (EPI == 1 || EPI == 2) { v0 += b0; v1 += b1; }
                if (EPI == 2) { v0 = gelu_exact(v0); v1 = gelu_exact(v1); }
                const size_t go = (size_t)row * N + col;
                if (EPI == 3) {
                    float2 r2 = *(const float2*)&res[go];
                    v0 += r2.x; v1 += r2.y;
                }
                if (SOUT == 0) {
                    *(float2*)&C[go] = make_float2(v0, v1);
                } else if (SOUT == 1) {
                    uint32_t ph, pl;
                    pack_hilo_b(ph, pl, v0, v1);
                    *(uint32_t*)&Cbh[go] = ph;
                    *(uint32_t*)&Cbl[go] = pl;
                } else {
                    uint32_t ph, pl;
                    pack_hilo_h(ph, pl, v0, v1);
                    *(uint32_t*)&Chh[go] = ph;
                    *(uint32_t*)&Chl[go] = pl;
                }
            }
        }
    }
}

template<int EPI, int SOUT>
__global__ void __launch_bounds__(512, 1) gemm_f16(
    const __half* __restrict__ Ah, const __half* __restrict__ Al,
    const __half* __restrict__ Wh,
    const float* __restrict__ bias, const float* __restrict__ res,
    float* __restrict__ C,
    __half* __restrict__ Chh, __half* __restrict__ Chl,
    int M, int N, int K)
{
    extern __shared__ __align__(128) char smem[];
    float acc[2][8][4];
    hgemm_core(acc, Ah, Al, Wh, blockIdx.y * TM, blockIdx.x * TN, K, smem_u32(smem));
    hgemm_epi<EPI, SOUT>(acc, bias, res, C, nullptr, nullptr, Chh, Chl,
                         blockIdx.y * TM, blockIdx.x * TN, N);
}

// merged QKV: blockIdx.z selects weight + output pair; outputs bf16 split
__global__ void __launch_bounds__(512, 1) gemm_qkv(
    const __half* __restrict__ Ah, const __half* __restrict__ Al,
    const __half* __restrict__ W0, const __half* __restrict__ W1,
    const __half* __restrict__ W2,
    __nv_bfloat16* __restrict__ o0h, __nv_bfloat16* __restrict__ o0l,
    __nv_bfloat16* __restrict__ o1h, __nv_bfloat16* __restrict__ o1l,
    __nv_bfloat16* __restrict__ o2h, __nv_bfloat16* __restrict__ o2l,
    int M, int N, int K)
{
    extern __shared__ __align__(128) char smem[];
    const int z = blockIdx.z;
    const __half* Wh = (z == 0) ? W0 : (z == 1) ? W1 : W2;
    __nv_bfloat16* oh = (z == 0) ? o0h : (z == 1) ? o1h : o2h;
    __nv_bfloat16* ol = (z == 0) ? o0l : (z == 1) ? o1l : o2l;
    float acc[2][8][4];
    hgemm_core(acc, Ah, Al, Wh, blockIdx.y * TM, blockIdx.x * TN, K, smem_u32(smem));
    hgemm_epi<0, 1>(acc, nullptr, nullptr, nullptr, oh, ol, nullptr, nullptr,
                    blockIdx.y * TM, blockIdx.x * TN, N);
}

// ============================================================================
// HMMA FlashAttention (bf16x3, unchanged math from R4) — outputs fp16 split o.
// ============================================================================
#define AT_ROW 144
#define AT_SUB (64 * AT_ROW)
#define AT_STAGE (4 * AT_SUB)
#define SMEM_ATT (2*AT_SUB + 2*AT_STAGE)

__device__ __forceinline__ void at_ldtile(
    uint32_t dsth, uint32_t dstl,
    const __nv_bfloat16* __restrict__ gh, const __nv_bfloat16* __restrict__ gl,
    size_t row0, int col0, int tid)
{
#pragma unroll
    for (int i = 0; i < 4; i++) {
        int idx = tid + i * 128;
        int r = idx >> 3, c = idx & 7;
        uint32_t so = r * AT_ROW + c * 16;
        size_t g = (row0 + r) * EE + col0 + c * 8;
        cp16(dsth + so, gh + g);
        cp16(dstl + so, gl + g);
    }
}

__global__ void __launch_bounds__(128, 1) attn_mma(
    const float* __restrict__ mask,
    const __nv_bfloat16* __restrict__ qh, const __nv_bfloat16* __restrict__ ql,
    const __nv_bfloat16* __restrict__ kh, const __nv_bfloat16* __restrict__ kl,
    const __nv_bfloat16* __restrict__ vh, const __nv_bfloat16* __restrict__ vl,
    __half* __restrict__ oh, __half* __restrict__ ol)
{
    extern __shared__ __align__(128) char smn[];
    const uint32_t sb = smem_u32(smn);
    const int qt = blockIdx.x, hd = blockIdx.y, b = blockIdx.z;
    const int tid = threadIdx.x;
    const int lane = tid & 31;
    const int w = tid >> 5;
    const int col0 = hd * 64;
    const size_t qrow0 = (size_t)b * SS + (size_t)qt * 64;

    const uint32_t QH = sb, QL = sb + AT_SUB;
    const uint32_t ST0 = sb + 2 * AT_SUB;

    at_ldtile(QH, QL, qh, ql, qrow0, col0, tid);
    {
        size_t kr = (size_t)b * SS;
        at_ldtile(ST0,            ST0 + AT_SUB,   kh, kl, kr, col0, tid);
        at_ldtile(ST0 + 2*AT_SUB, ST0 + 3*AT_SUB, vh, vl, kr, col0, tid);
    }
    cp_commit();
    {
        size_t kr = (size_t)b * SS + 64;
        uint32_t s1 = ST0 + AT_STAGE;
        at_ldtile(s1,            s1 + AT_SUB,   kh, kl, kr, col0, tid);
        at_ldtile(s1 + 2*AT_SUB, s1 + 3*AT_SUB, vh, vl, kr, col0, tid);
    }
    cp_commit();
    cp_wait<1>();
    __syncthreads();

    uint32_t fqh[4][4], fql[4][4];
    {
        uint32_t qa = QH + (w * 16 + (lane & 15)) * AT_ROW + (lane >> 4) * 16;
#pragma unroll
        for (int c = 0; c < 4; c++) {
            ldsm4(fqh[c][0], fqh[c][1], fqh[c][2], fqh[c][3], qa + c * 32);
            ldsm4(fql[c][0], fql[c][1], fql[c][2], fql[c][3], qa + c * 32 + AT_SUB);
        }
    }

    float oacc[8][4];
#pragma unroll
    for (int t = 0; t < 8; t++)
#pragma unroll
        for (int r = 0; r < 4; r++) oacc[t][r] = 0.f;
    float rmax0 = -1e30f, rmax1 = -1e30f, rsum0 = 0.f, rsum1 = 0.f;

    const float* mrow0 = mask + ((size_t)b * SS + qt * 64 + w * 16 + (lane >> 2)) * SS
                              + (lane & 3) * 2;
    const float* mrow1 = mrow0 + 8 * SS;

    for (int kt = 0; kt < 16; kt++) {
        if (kt > 0) {
            if (kt + 1 < 16) {
                size_t kr = (size_t)b * SS + (size_t)(kt + 1) * 64;
                uint32_t s1 = ST0 + ((kt + 1) & 1) * AT_STAGE;
                at_ldtile(s1,            s1 + AT_SUB,   kh, kl, kr, col0, tid);
                at_ldtile(s1 + 2*AT_SUB, s1 + 3*AT_SUB, vh, vl, kr, col0, tid);
                cp_commit();
                cp_wait<1>();
            } else {
                cp_wait<0>();
            }
            __syncthreads();
        }

        const uint32_t kb = ST0 + (kt & 1) * AT_STAGE;
        const uint32_t vb = kb + 2 * AT_SUB;

        float sacc[8][4];
#pragma unroll
        for (int t = 0; t < 8; t++)
#pragma unroll
            for (int r = 0; r < 4; r++) sacc[t][r] = 0.f;

#pragma unroll
        for (int c = 0; c < 4; c++) {
#pragma unroll
            for (int np = 0; np < 4; np++) {
                uint32_t ka = kb + (np * 16 + ((lane >> 4) << 3) + (lane & 7)) * AT_ROW
                            + ((lane >> 3) & 1) * 16 + c * 32;
                uint32_t bh[4], bl[4];
                ldsm4(bh[0], bh[1], bh[2], bh[3], ka);
                ldsm4(bl[0], bl[1], bl[2], bl[3], ka + AT_SUB);
                mma_bf16(sacc[2*np],   fqh[c], &bh[0]);
                mma_bf16(sacc[2*np],   fqh[c], &bl[0]);
                mma_bf16(sacc[2*np],   fql[c], &bh[0]);
                mma_bf16(sacc[2*np+1], fqh[c], &bh[2]);
                mma_bf16(sacc[2*np+1], fqh[c], &bl[2]);
                mma_bf16(sacc[2*np+1], fql[c], &bh[2]);
            }
        }

        const float* mk0 = mrow0 + kt * 64;
        const float* mk1 = mrow1 + kt * 64;
        float tmax0 = -1e30f, tmax1 = -1e30f;
#pragma unroll
        for (int t = 0; t < 8; t++) {
            float2 ma = *(const float2*)(mk0 + t * 8);
            float2 mb = *(const float2*)(mk1 + t * 8);
            sacc[t][0] = sacc[t][0] * 0.125f * ma.x;
            sacc[t][1] = sacc[t][1] * 0.125f * ma.y;
            sacc[t][2] = sacc[t][2] * 0.125f * mb.x;
            sacc[t][3] = sacc[t][3] * 0.125f * mb.y;
            tmax0 = fmaxf(tmax0, fmaxf(sacc[t][0], sacc[t][1]));
            tmax1 = fmaxf(tmax1, fmaxf(sacc[t][2], sacc[t][3]));
        }
        tmax0 = fmaxf(tmax0, __shfl_xor_sync(0xffffffffu, tmax0, 1));
        tmax0 = fmaxf(tmax0, __shfl_xor_sync(0xffffffffu, tmax0, 2));
        tmax1 = fmaxf(tmax1, __shfl_xor_sync(0xffffffffu, tmax1, 1));
        tmax1 = fmaxf(tmax1, __shfl_xor_sync(0xffffffffu, tmax1, 2));
        float nmax0 = fmaxf(rmax0, tmax0), nmax1 = fmaxf(rmax1, tmax1);
        float corr0 = __expf(rmax0 - nmax0), corr1 = __expf(rmax1 - nmax1);
        rmax0 = nmax0; rmax1 = nmax1;

        float ts0 = 0.f, ts1 = 0.f;
#pragma unroll
        for (int t = 0; t < 8; t++) {
            float2 ma = *(const float2*)(mk0 + t * 8);
            float2 mb = *(const float2*)(mk1 + t * 8);
            float e0 = __expf(sacc[t][0] - nmax0) * ma.x;
            float e1 = __expf(sacc[t][1] - nmax0) * ma.y;
            float e2 = __expf(sacc[t][2] - nmax1) * mb.x;
            float e3 = __expf(sacc[t][3] - nmax1) * mb.y;
            ts0 += e0 + e1; ts1 += e2 + e3;
            sacc[t][0] = e0; sacc[t][1] = e1; sacc[t][2] = e2; sacc[t][3] = e3;
        }
        ts0 += __shfl_xor_sync(0xffffffffu, ts0, 1);
        ts0 += __shfl_xor_sync(0xffffffffu, ts0, 2);
        ts1 += __shfl_xor_sync(0xffffffffu, ts1, 1);
        ts1 += __shfl_xor_sync(0xffffffffu, ts1, 2);
        rsum0 = rsum0 * corr0 + ts0;
        rsum1 = rsum1 * corr1 + ts1;
#pragma unroll
        for (int t = 0; t < 8; t++) {
            oacc[t][0] *= corr0; oacc[t][1] *= corr0;
            oacc[t][2] *= corr1; oacc[t][3] *= corr1;
        }

#pragma unroll
        for (int c = 0; c < 4; c++) {
            uint32_t pah[4], pal[4];
            pack_hilo_b(pah[0], pal[0], sacc[2*c][0],   sacc[2*c][1]);
            pack_hilo_b(pah[1], pal[1], sacc[2*c][2],   sacc[2*c][3]);
            pack_hilo_b(pah[2], pal[2], sacc[2*c+1][0], sacc[2*c+1][1]);
            pack_hilo_b(pah[3], pal[3], sacc[2*c+1][2], sacc[2*c+1][3]);
#pragma unroll
            for (int nd = 0; nd < 4; nd++) {
                uint32_t va = vb + (c * 16 + ((lane >> 3) & 1) * 8 + (lane & 7)) * AT_ROW
                            + nd * 32 + (lane >> 4) * 16;
                uint32_t wh[4], wl[4];
                ldsm4t(wh[0], wh[1], wh[2], wh[3], va);
                ldsm4t(wl[0], wl[1], wl[2], wl[3], va + AT_SUB);
                mma_bf16(oacc[2*nd],   pah, &wh[0]);
                mma_bf16(oacc[2*nd],   pah, &wl[0]);
                mma_bf16(oacc[2*nd],   pal, &wh[0]);
                mma_bf16(oacc[2*nd+1], pah, &wh[2]);
                mma_bf16(oacc[2*nd+1], pah, &wl[2]);
                mma_bf16(oacc[2*nd+1], pal, &wh[2]);
            }
        }
        __syncthreads();
    }

    const float inv0 = 1.0f / (rsum0 + 1e-20f);
    const float inv1 = 1.0f / (rsum1 + 1e-20f);
    const size_t r0g = qrow0 + w * 16 + (lane >> 2);
    const size_t r1g = r0g + 8;
#pragma unroll
    for (int t = 0; t < 8; t++) {
        const int col = col0 + t * 8 + (lane & 3) * 2;
        uint32_t ph, pl;
        pack_hilo_h(ph, pl, oacc[t][0] * inv0, oacc[t][1] * inv0);
        *(uint32_t*)&oh[r0g * EE + col] = ph;
        *(uint32_t*)&ol[r0g * EE + col] = pl;
        pack_hilo_h(ph, pl, oacc[t][2] * inv1, oacc[t][3] * inv1);
        *(uint32_t*)&oh[r1g * EE + col] = ph;
        *(uint32_t*)&ol[r1g * EE + col] = pl;
    }
}

// ============================================================================
// LayerNorm over E=1024; optional gated residual; optional fp16 split output.
// ============================================================================
__global__ void __launch_bounds__(256) ln_kernel(
    const float* __restrict__ x, const float* __restrict__ f,
    const float* __restrict__ mask, const float* __restrict__ gamma,
    const float* __restrict__ beta, float* __restrict__ out,
    __half* __restrict__ outh, __half* __restrict__ outl, int useF)
{
    const int row = blockIdx.x;
    const int tid = threadIdx.x;

    float4 v4 = *(const float4*)&x[(size_t)row * EE + tid * 4];
    float v[4] = {v4.x, v4.y, v4.z, v4.w};

    if (useF) {
        const int b = row / SS, s = row % SS;
        const float gate = mask[((size_t)b * SS + (SS - 1)) * SS + s];
        float4 f4 = *(const float4*)&f[(size_t)row * EE + tid * 4];
        v[0] += f4.x * gate; v[1] += f4.y * gate;
        v[2] += f4.z * gate; v[3] += f4.w * gate;
    }

    float s1 = v[0] + v[1] + v[2] + v[3];
    float s2 = v[0]*v[0] + v[1]*v[1] + v[2]*v[2] + v[3]*v[3];
#pragma unroll
    for (int ofs = 16; ofs >= 1; ofs >>= 1) {
        s1 += __shfl_xor_sync(0xffffffffu, s1, ofs);
        s2 += __shfl_xor_sync(0xffffffffu, s2, ofs);
    }
    __shared__ float red1[8], red2[8];
    if ((tid & 31) == 0) { red1[tid >> 5] = s1; red2[tid >> 5] = s2; }
    __syncthreads();
    float t1 = 0.f, t2 = 0.f;
#pragma unroll
    for (int wv = 0; wv < 8; wv++) { t1 += red1[wv]; t2 += red2[wv]; }

    const float mean = t1 * (1.0f / EE);
    const float var  = t2 * (1.0f / EE) - mean * mean;
    const float inv  = rsqrtf(var + 1e-5f);

    float4 g4 = *(const float4*)&gamma[tid * 4];
    float4 b4 = *(const float4*)&beta[tid * 4];
    float o0 = (v[0] - mean) * inv * g4.x + b4.x;
    float o1 = (v[1] - mean) * inv * g4.y + b4.y;
    float o2 = (v[2] - mean) * inv * g4.z + b4.z;
    float o3 = (v[3] - mean) * inv * g4.w + b4.w;
    if (out)
        *(float4*)&out[(size_t)row * EE + tid * 4] = make_float4(o0, o1, o2, o3);
    if (outh) {
        uint32_t h0, l0, h1, l1;
        pack_hilo_h(h0, l0, o0, o1);
        pack_hilo_h(h1, l1, o2, o3);
        const size_t go = (size_t)row * EE + tid * 4;
        *(uint32_t*)&outh[go]     = h0;
        *(uint32_t*)&outh[go + 2] = h1;
        *(uint32_t*)&outl[go]     = l0;
        *(uint32_t*)&outl[go + 2] = l1;
    }
}

// ============================================================================
extern "C" void kernel_launch(void* const* d_in, const int* in_sizes, int n_in,
                              void* d_out, int out_size)
{
    const float* h    = (const float*)d_in[0];
    const float* mask = (const float*)d_in[1];
    const float* wq   = (const float*)d_in[2];
    const float* wk   = (const float*)d_in[3];
    const float* wv   = (const float*)d_in[4];
    const float* wmh  = (const float*)d_in[5];
    const float* g1   = (const float*)d_in[6];
    const float* be1  = (const float*)d_in[7];
    const float* w1   = (const float*)d_in[8];
    const float* b1   = (const float*)d_in[9];
    const float* w2   = (const float*)d_in[10];
    const float* b2   = (const float*)d_in[11];
    const float* g2   = (const float*)d_in[12];
    const float* be2  = (const float*)d_in[13];
    float* out = (float*)d_out;

    float *h2, *a, *f;
    cudaGetSymbolAddress((void**)&h2, g_h2);
    cudaGetSymbolAddress((void**)&a,  g_a);
    cudaGetSymbolAddress((void**)&f,  g_f);

    __half *hh, *hl, *oh, *ol, *ah, *al, *hdh, *hdl;
    __half *w16q, *w16k, *w16v, *w16m, *w16a, *w16b;
    cudaGetSymbolAddress((void**)&hh,  g_hh);   cudaGetSymbolAddress((void**)&hl,  g_hl);
    cudaGetSymbolAddress((void**)&oh,  g_oh);   cudaGetSymbolAddress((void**)&ol,  g_ol);
    cudaGetSymbolAddress((void**)&ah,  g_ah);   cudaGetSymbolAddress((void**)&al,  g_al);
    cudaGetSymbolAddress((void**)&hdh, g_hidh); cudaGetSymbolAddress((void**)&hdl, g_hidl);
    cudaGetSymbolAddress((void**)&w16q, g_w16q); cudaGetSymbolAddress((void**)&w16k, g_w16k);
    cudaGetSymbolAddress((void**)&w16v, g_w16v); cudaGetSymbolAddress((void**)&w16m, g_w16m);
    cudaGetSymbolAddress((void**)&w16a, g_w16a); cudaGetSymbolAddress((void**)&w16b, g_w16b);

    __nv_bfloat16 *qbh, *qbl, *kbh, *kbl, *vbh, *vbl;
    cudaGetSymbolAddress((void**)&qbh, g_qbh); cudaGetSymbolAddress((void**)&qbl, g_qbl);
    cudaGetSymbolAddress((void**)&kbh, g_kbh); cudaGetSymbolAddress((void**)&kbl, g_kbl);
    cudaGetSymbolAddress((void**)&vbh, g_vbh); cudaGetSymbolAddress((void**)&vbl, g_vbl);

    cudaFuncSetAttribute(attn_mma, cudaFuncAttributeMaxDynamicSharedMemorySize, SMEM_ATT);
    cudaFuncSetAttribute(gemm_qkv, cudaFuncAttributeMaxDynamicSharedMemorySize, SMEM_MMA);
    cudaFuncSetAttribute(gemm_f16<3,0>, cudaFuncAttributeMaxDynamicSharedMemorySize, SMEM_MMA);
    cudaFuncSetAttribute(gemm_f16<2,2>, cudaFuncAttributeMaxDynamicSharedMemorySize, SMEM_MMA);
    cudaFuncSetAttribute(gemm_f16<1,0>, cudaFuncAttributeMaxDynamicSharedMemorySize, SMEM_MMA);

    // input split + weight converts
    {
        int n4 = MTOK * EE / 4;
        split16_kernel<<<(n4 + 255) / 256, 256>>>(h, hh, hl, n4);
        int w4 = EE * EE / 4;
        cvt16_kernel<<<(w4 + 255) / 256, 256>>>(wq,  w16q, w4);
        cvt16_kernel<<<(w4 + 255) / 256, 256>>>(wk,  w16k, w4);
        cvt16_kernel<<<(w4 + 255) / 256, 256>>>(wv,  w16v, w4);
        cvt16_kernel<<<(w4 + 255) / 256, 256>>>(wmh, w16m, w4);
        int v4a = HIDD * EE / 4;
        cvt16_kernel<<<(v4a + 255) / 256, 256>>>(w1, w16a, v4a);
        cvt16_kernel<<<(v4a + 255) / 256, 256>>>(w2, w16b, v4a);
    }

    dim3 blk(512);
    dim3 gQKV(EE / TN, MTOK / TM, 3);   // (4, 64, 3)
    dim3 gE(EE / TN, MTOK / TM);        // (4, 64)
    dim3 gHid(HIDD / TN, MTOK / TM);    // (16, 64)

    // QKV merged -> bf16 splits
    gemm_qkv<<<gQKV, blk, SMEM_MMA>>>(hh, hl, w16q, w16k, w16v,
                                      qbh, qbl, kbh, kbl, vbh, vbl, MTOK, EE, EE);

    // attention -> o (fp16 split)
    attn_mma<<<dim3(SS / 64, HH, BB), dim3(128), SMEM_ATT>>>(
        mask, qbh, qbl, kbh, kbl, vbh, vbl, oh, ol);

    // mh + residual -> h2 (fp32)
    gemm_f16<3,0><<<gE, blk, SMEM_MMA>>>(oh, ol, w16m, nullptr, h,
                                         h2, nullptr, nullptr, MTOK, EE, EE);

    // attn_norm -> a fp32 + fp16 split
    ln_kernel<<<MTOK, 256>>>(h2, nullptr, nullptr, g1, be1, a, ah, al, 0);

    // FFN1 (+bias+GELU) -> hid fp16 split
    gemm_f16<2,2><<<gHid, blk, SMEM_MMA>>>(ah, al, w16a, b1, nullptr,
                                           nullptr, hdh, hdl, MTOK, HIDD, EE);
    // FFN2 (+bias) -> f fp32
    gemm_f16<1,0><<<gE, blk, SMEM_MMA>>>(hdh, hdl, w16b, b2, nullptr,
                                         f, nullptr, nullptr, MTOK, EE, HIDD);

    // gated residual + ffn_norm -> out
    ln_kernel<<<MTOK, 256>>>(a, f, mask, g2, be2, out, nullptr, nullptr, 1);
}

// round 6
// speedup vs baseline: 6.0635x; 1.5946x over previous
#include <cuda_runtime.h>
#include <cuda_fp16.h>
#include <math.h>
#include <stdint.h>

#define BB   8
#define SS   1024
#define EE   1024
#define HH   16
#define DHH  64
#define HIDD 4096
#define MTOK (BB*SS)   // 8192 token rows

// ---------------- fp32 scratch ---------------------------------------------
__device__ float g_h2 [(size_t)MTOK*EE];
__device__ float g_a  [(size_t)MTOK*EE];
__device__ float g_f  [(size_t)MTOK*EE];

// ---------------- fp16 activations ------------------------------------------
__device__ __half g_h16 [(size_t)MTOK*EE];
__device__ __half g_q16 [(size_t)MTOK*EE];
__device__ __half g_k16 [(size_t)MTOK*EE];
__device__ __half g_v16 [(size_t)MTOK*EE];
__device__ __half g_o16 [(size_t)MTOK*EE];
__device__ __half g_a16 [(size_t)MTOK*EE];
__device__ __half g_hid16[(size_t)MTOK*HIDD];

// ---------------- fp16 weights ----------------------------------------------
__device__ __half g_w16q[(size_t)EE*EE];
__device__ __half g_w16k[(size_t)EE*EE];
__device__ __half g_w16v[(size_t)EE*EE];
__device__ __half g_w16m[(size_t)EE*EE];
__device__ __half g_w16a[(size_t)HIDD*EE];
__device__ __half g_w16b[(size_t)EE*HIDD];

__device__ __forceinline__ float gelu_exact(float x) {
    return 0.5f * x * (1.0f + erff(x * 0.70710678118654752f));
}

// ============================ PTX helpers (sm_100-safe) =====================
__device__ __forceinline__ uint32_t smem_u32(const void* p) {
    uint32_t a;
    asm("{ .reg .u64 t; cvta.to.shared.u64 t, %1; cvt.u32.u64 %0, t; }"
        : "=r"(a) : "l"(p));
    return a;
}
__device__ __forceinline__ void cp16(uint32_t s, const void* g) {
    asm volatile("cp.async.cg.shared.global [%0], [%1], 16;" :: "r"(s), "l"(g));
}
__device__ __forceinline__ void cp_commit() {
    asm volatile("cp.async.commit_group;" ::: "memory");
}
template<int N>
__device__ __forceinline__ void cp_wait() {
    asm volatile("cp.async.wait_group %0;" :: "n"(N) : "memory");
}
__device__ __forceinline__ void ldsm4(uint32_t& r0, uint32_t& r1,
                                      uint32_t& r2, uint32_t& r3, uint32_t a) {
    asm volatile("ldmatrix.sync.aligned.m8n8.x4.shared.b16 {%0,%1,%2,%3}, [%4];"
                 : "=r"(r0), "=r"(r1), "=r"(r2), "=r"(r3) : "r"(a));
}
__device__ __forceinline__ void ldsm4t(uint32_t& r0, uint32_t& r1,
                                       uint32_t& r2, uint32_t& r3, uint32_t a) {
    asm volatile("ldmatrix.sync.aligned.m8n8.x4.trans.shared.b16 {%0,%1,%2,%3}, [%4];"
                 : "=r"(r0), "=r"(r1), "=r"(r2), "=r"(r3) : "r"(a));
}
__device__ __forceinline__ void mma_f16(float* d, const uint32_t* a, const uint32_t* b) {
    asm volatile(
        "mma.sync.aligned.m16n8k16.row.col.f32.f16.f16.f32 "
        "{%0,%1,%2,%3}, {%4,%5,%6,%7}, {%8,%9}, {%0,%1,%2,%3};"
        : "+f"(d[0]), "+f"(d[1]), "+f"(d[2]), "+f"(d[3])
        : "r"(a[0]), "r"(a[1]), "r"(a[2]), "r"(a[3]), "r"(b[0]), "r"(b[1]));
}
__device__ __forceinline__ uint32_t pack2h(float a, float b) {
    __half2 v = __halves2half2(__float2half_rn(a), __float2half_rn(b));
    return *(uint32_t*)&v;
}

// ============================================================================
// cvt: fp32 -> fp16 (round)
// ============================================================================
__global__ void __launch_bounds__(256) cvt16_kernel(
    const float* __restrict__ x, __half* __restrict__ y, int n4)
{
    int i = blockIdx.x * 256 + threadIdx.x;
    if (i >= n4) return;
    float4 v = ((const float4*)x)[i];
    ((uint32_t*)y)[2*i]   = pack2h(v.x, v.y);
    ((uint32_t*)y)[2*i+1] = pack2h(v.z, v.w);
}

// ============================================================================
// fp16 GEMM core: C[M,N] = A[M,K] @ W[N,K]^T, fp32 accumulate, single pass.
// CTA 128x256, BK=32, 512 threads (16 warps 4x4, warp tile 32x64), 3 stages.
// ============================================================================
#define TM 128
#define TN 256
#define BK 32
#define ROWB 80
#define A_SUB (128 * ROWB)          // 10240 B
#define W_SUB (256 * ROWB)          // 20480 B
#define STG   (A_SUB + W_SUB)       // 30720 B
#define SMEM_MMA (3 * STG)          // 92160 B

__device__ __forceinline__ void hgemm_core(
    float acc[2][8][4],
    const __half* __restrict__ A, const __half* __restrict__ W,
    int m0, int n0, int K, uint32_t sb)
{
    const int tid  = threadIdx.x;
    const int lane = tid & 31;
    const int wid  = tid >> 5;
    const int wm   = wid & 3;
    const int wn   = wid >> 2;

    const int lr = tid >> 2, lc = tid & 3;
    const size_t   ga   = (size_t)(m0 + lr) * K + lc * 8;
    const uint32_t aso  = lr * ROWB + lc * 16;
    const size_t   gw0  = (size_t)(n0 + lr) * K + lc * 8;
    const size_t   gw1  = gw0 + (size_t)128 * K;
    const uint32_t wso0 = lr * ROWB + lc * 16;
    const uint32_t wso1 = wso0 + 128 * ROWB;

    const uint32_t a_row  = wm * 32 + (lane & 15);
    const uint32_t a_coff = (lane >> 4) * 16;
    const uint32_t b_row  = wn * 64 + ((lane >> 4) << 3) + (lane & 7);
    const uint32_t b_coff = ((lane >> 3) & 1) * 16;

#pragma unroll
    for (int mt = 0; mt < 2; mt++)
#pragma unroll
        for (int nt = 0; nt < 8; nt++)
#pragma unroll
            for (int r = 0; r < 4; r++) acc[mt][nt][r] = 0.f;

    const int nst = K / BK;
#pragma unroll
    for (int s = 0; s < 2; s++) {
        const uint32_t b = sb + s * STG;
        const int k0 = s * BK;
        cp16(b + aso,           A + ga  + k0);
        cp16(b + A_SUB + wso0,  W + gw0 + k0);
        cp16(b + A_SUB + wso1,  W + gw1 + k0);
        cp_commit();
    }

    int sbuf = 0;
    for (int s = 0; s < nst; s++) {
        cp_wait<1>();
        __syncthreads();

        if (s + 2 < nst) {
            const int nb = (sbuf + 2 >= 3) ? sbuf - 1 : sbuf + 2;
            const uint32_t b = sb + nb * STG;
            const int k0 = (s + 2) * BK;
            cp16(b + aso,          A + ga  + k0);
            cp16(b + A_SUB + wso0, W + gw0 + k0);
            cp16(b + A_SUB + wso1, W + gw1 + k0);
            cp_commit();
        }

        const uint32_t bbase = sb + sbuf * STG;
#pragma unroll
        for (int kk = 0; kk < 2; kk++) {
            uint32_t af[2][4];
#pragma unroll
            for (int mt = 0; mt < 2; mt++) {
                uint32_t ad = bbase + (a_row + mt * 16) * ROWB + a_coff + kk * 32;
                ldsm4(af[mt][0], af[mt][1], af[mt][2], af[mt][3], ad);
            }
            uint32_t bf[4][4];
#pragma unroll
            for (int np = 0; np < 4; np++) {
                uint32_t bd = bbase + A_SUB + (b_row + np * 16) * ROWB + b_coff + kk * 32;
                ldsm4(bf[np][0], bf[np][1], bf[np][2], bf[np][3], bd);
            }
#pragma unroll
            for (int mt = 0; mt < 2; mt++)
#pragma unroll
                for (int nt = 0; nt < 8; nt++)
                    mma_f16(acc[mt][nt], af[mt], &bf[nt >> 1][(nt & 1) * 2]);
        }
        __syncthreads();
        sbuf = (sbuf + 1 >= 3) ? 0 : sbuf + 1;
    }
}

// EPI: 0=none,1=+bias,2=+bias+GELU,3=+res ; SOUT: 0=fp32, 1=fp16
template<int EPI, int SOUT>
__device__ __forceinline__ void hgemm_epi(
    float acc[2][8][4], const float* __restrict__ bias, const float* __restrict__ res,
    float* __restrict__ C, __half* __restrict__ C16,
    int m0, int n0, int N)
{
    const int lane = threadIdx.x & 31;
    const int wid  = threadIdx.x >> 5;
    const int wm   = wid & 3, wn = wid >> 2;
#pragma unroll
    for (int mt = 0; mt < 2; mt++) {
        const int rowA = m0 + wm * 32 + mt * 16 + (lane >> 2);
#pragma unroll
        for (int nt = 0; nt < 8; nt++) {
            const int col = n0 + wn * 64 + nt * 8 + (lane & 3) * 2;
            float b0 = 0.f, b1 = 0.f;
            if (EPI == 1 || EPI == 2) { b0 = bias[col]; b1 = bias[col + 1]; }
#pragma unroll
            for (int hf = 0; hf < 2; hf++) {
                const int row = rowA + hf * 8;
                float v0 = acc[mt][nt][hf * 2 + 0];
                float v1 = acc[mt][nt][hf * 2 + 1];
                if (EPI == 1 || EPI == 2) { v0 += b0; v1 += b1; }
                if (EPI == 2) { v0 = gelu_exact(v0); v1 = gelu_exact(v1); }
                const size_t go = (size_t)row * N + col;
                if (EPI == 3) {
                    float2 r2 = *(const float2*)&res[go];
                    v0 += r2.x; v1 += r2.y;
                }
                if (SOUT == 0) {
                    *(float2*)&C[go] = make_float2(v0, v1);
                } else {
                    *(uint32_t*)&C16[go] = pack2h(v0, v1);
                }
            }
        }
    }
}

template<int EPI, int SOUT>
__global__ void __launch_bounds__(512, 1) gemm_f16(
    const __half* __restrict__ A, const __half* __restrict__ W,
    const float* __restrict__ bias, const float* __restrict__ res,
    float* __restrict__ C, __half* __restrict__ C16,
    int M, int N, int K)
{
    extern __shared__ __align__(128) char smem[];
    float acc[2][8][4];
    hgemm_core(acc, A, W, blockIdx.y * TM, blockIdx.x * TN, K, smem_u32(smem));
    hgemm_epi<EPI, SOUT>(acc, bias, res, C, C16, blockIdx.y * TM, blockIdx.x * TN, N);
}

// merged QKV: blockIdx.z selects weight + output
__global__ void __launch_bounds__(512, 1) gemm_qkv(
    const __half* __restrict__ A,
    const __half* __restrict__ W0, const __half* __restrict__ W1,
    const __half* __restrict__ W2,
    __half* __restrict__ o0, __half* __restrict__ o1, __half* __restrict__ o2,
    int M, int N, int K)
{
    extern __shared__ __align__(128) char smem[];
    const int z = blockIdx.z;
    const __half* W = (z == 0) ? W0 : (z == 1) ? W1 : W2;
    __half* O = (z == 0) ? o0 : (z == 1) ? o1 : o2;
    float acc[2][8][4];
    hgemm_core(acc, A, W, blockIdx.y * TM, blockIdx.x * TN, K, smem_u32(smem));
    hgemm_epi<0, 1>(acc, nullptr, nullptr, nullptr, O, blockIdx.y * TM, blockIdx.x * TN, N);
}

// ============================================================================
// fp16 HMMA FlashAttention: CTA = (qtile 64, head, batch), 128 threads.
// Single-pass fp16 QK^T and PV; fp32 online masked softmax (faithful renorm).
// ============================================================================
#define AT_ROW 144
#define AT_SUB (64 * AT_ROW)             // 9216 B
#define AT_STG (2 * AT_SUB)              // K | V
#define SMEM_ATT (AT_SUB + 2 * AT_STG)   // Q + 2 stages = 46080 B

__device__ __forceinline__ void at_ld(
    uint32_t dst, const __half* __restrict__ g, size_t row0, int col0, int tid)
{
#pragma unroll
    for (int i = 0; i < 4; i++) {
        int idx = tid + i * 128;
        int r = idx >> 3, c = idx & 7;
        cp16(dst + r * AT_ROW + c * 16, g + (row0 + r) * EE + col0 + c * 8);
    }
}

__global__ void __launch_bounds__(128, 1) attn_mma(
    const float* __restrict__ mask,
    const __half* __restrict__ q16, const __half* __restrict__ k16,
    const __half* __restrict__ v16, __half* __restrict__ o16)
{
    extern __shared__ __align__(128) char smn[];
    const uint32_t sb = smem_u32(smn);
    const int qt = blockIdx.x, hd = blockIdx.y, b = blockIdx.z;
    const int tid = threadIdx.x;
    const int lane = tid & 31;
    const int w = tid >> 5;
    const int col0 = hd * 64;
    const size_t qrow0 = (size_t)b * SS + (size_t)qt * 64;

    const uint32_t QS  = sb;
    const uint32_t ST0 = sb + AT_SUB;

    at_ld(QS, q16, qrow0, col0, tid);
    at_ld(ST0,          k16, (size_t)b * SS, col0, tid);
    at_ld(ST0 + AT_SUB, v16, (size_t)b * SS, col0, tid);
    cp_commit();
    at_ld(ST0 + AT_STG,          k16, (size_t)b * SS + 64, col0, tid);
    at_ld(ST0 + AT_STG + AT_SUB, v16, (size_t)b * SS + 64, col0, tid);
    cp_commit();
    cp_wait<1>();
    __syncthreads();

    uint32_t fq[4][4];
    {
        uint32_t qa = QS + (w * 16 + (lane & 15)) * AT_ROW + (lane >> 4) * 16;
#pragma unroll
        for (int c = 0; c < 4; c++)
            ldsm4(fq[c][0], fq[c][1], fq[c][2], fq[c][3], qa + c * 32);
    }

    float oacc[8][4];
#pragma unroll
    for (int t = 0; t < 8; t++)
#pragma unroll
        for (int r = 0; r < 4; r++) oacc[t][r] = 0.f;
    float rmax0 = -1e30f, rmax1 = -1e30f, rsum0 = 0.f, rsum1 = 0.f;

    const float* mrow0 = mask + ((size_t)b * SS + qt * 64 + w * 16 + (lane >> 2)) * SS
                              + (lane & 3) * 2;
    const float* mrow1 = mrow0 + 8 * SS;

    for (int kt = 0; kt < 16; kt++) {
        if (kt > 0) {
            if (kt + 1 < 16) {
                uint32_t s1 = ST0 + ((kt + 1) & 1) * AT_STG;
                size_t kr = (size_t)b * SS + (size_t)(kt + 1) * 64;
                at_ld(s1,          k16, kr, col0, tid);
                at_ld(s1 + AT_SUB, v16, kr, col0, tid);
                cp_commit();
                cp_wait<1>();
            } else {
                cp_wait<0>();
            }
            __syncthreads();
        }

        const uint32_t kb = ST0 + (kt & 1) * AT_STG;
        const uint32_t vb = kb + AT_SUB;

        // ---- scores = Q K^T ----
        float sacc[8][4];
#pragma unroll
        for (int t = 0; t < 8; t++)
#pragma unroll
            for (int r = 0; r < 4; r++) sacc[t][r] = 0.f;

#pragma unroll
        for (int c = 0; c < 4; c++) {
#pragma unroll
            for (int np = 0; np < 4; np++) {
                uint32_t ka = kb + (np * 16 + ((lane >> 4) << 3) + (lane & 7)) * AT_ROW
                            + ((lane >> 3) & 1) * 16 + c * 32;
                uint32_t kf[4];
                ldsm4(kf[0], kf[1], kf[2], kf[3], ka);
                mma_f16(sacc[2*np],   fq[c], &kf[0]);
                mma_f16(sacc[2*np+1], fq[c], &kf[2]);
            }
        }

        // ---- online masked softmax ----
        const float* mk0 = mrow0 + kt * 64;
        const float* mk1 = mrow1 + kt * 64;
        float tmax0 = -1e30f, tmax1 = -1e30f;
#pragma unroll
        for (int t = 0; t < 8; t++) {
            float2 ma = *(const float2*)(mk0 + t * 8);
            float2 mb = *(const float2*)(mk1 + t * 8);
            sacc[t][0] = sacc[t][0] * 0.125f * ma.x;
            sacc[t][1] = sacc[t][1] * 0.125f * ma.y;
            sacc[t][2] = sacc[t][2] * 0.125f * mb.x;
            sacc[t][3] = sacc[t][3] * 0.125f * mb.y;
            tmax0 = fmaxf(tmax0, fmaxf(sacc[t][0], sacc[t][1]));
            tmax1 = fmaxf(tmax1, fmaxf(sacc[t][2], sacc[t][3]));
        }
        tmax0 = fmaxf(tmax0, __shfl_xor_sync(0xffffffffu, tmax0, 1));
        tmax0 = fmaxf(tmax0, __shfl_xor_sync(0xffffffffu, tmax0, 2));
        tmax1 = fmaxf(tmax1, __shfl_xor_sync(0xffffffffu, tmax1, 1));
        tmax1 = fmaxf(tmax1, __shfl_xor_sync(0xffffffffu, tmax1, 2));
        float nmax0 = fmaxf(rmax0, tmax0), nmax1 = fmaxf(rmax1, tmax1);
        float corr0 = __expf(rmax0 - nmax0), corr1 = __expf(rmax1 - nmax1);
        rmax0 = nmax0; rmax1 = nmax1;

        float ts0 = 0.f, ts1 = 0.f;
#pragma unroll
        for (int t = 0; t < 8; t++) {
            float2 ma = *(const float2*)(mk0 + t * 8);
            float2 mb = *(const float2*)(mk1 + t * 8);
            float e0 = __expf(sacc[t][0] - nmax0) * ma.x;
            float e1 = __expf(sacc[t][1] - nmax0) * ma.y;
            float e2 = __expf(sacc[t][2] - nmax1) * mb.x;
            float e3 = __expf(sacc[t][3] - nmax1) * mb.y;
            ts0 += e0 + e1; ts1 += e2 + e3;
            sacc[t][0] = e0; sacc[t][1] = e1; sacc[t][2] = e2; sacc[t][3] = e3;
        }
        ts0 += __shfl_xor_sync(0xffffffffu, ts0, 1);
        ts0 += __shfl_xor_sync(0xffffffffu, ts0, 2);
        ts1 += __shfl_xor_sync(0xffffffffu, ts1, 1);
        ts1 += __shfl_xor_sync(0xffffffffu, ts1, 2);
        rsum0 = rsum0 * corr0 + ts0;
        rsum1 = rsum1 * corr1 + ts1;
#pragma unroll
        for (int t = 0; t < 8; t++) {
            oacc[t][0] *= corr0; oacc[t][1] *= corr0;
            oacc[t][2] *= corr1; oacc[t][3] *= corr1;
        }

        // ---- O += P V ----
#pragma unroll
        for (int c = 0; c < 4; c++) {
            uint32_t pa[4];
            pa[0] = pack2h(sacc[2*c][0],   sacc[2*c][1]);
            pa[1] = pack2h(sacc[2*c][2],   sacc[2*c][3]);
            pa[2] = pack2h(sacc[2*c+1][0], sacc[2*c+1][1]);
            pa[3] = pack2h(sacc[2*c+1][2], sacc[2*c+1][3]);
#pragma unroll
            for (int nd = 0; nd < 4; nd++) {
                uint32_t va = vb + (c * 16 + ((lane >> 3) & 1) * 8 + (lane & 7)) * AT_ROW
                            + nd * 32 + (lane >> 4) * 16;
                uint32_t vf[4];
                ldsm4t(vf[0], vf[1], vf[2], vf[3], va);
                mma_f16(oacc[2*nd],   pa, &vf[0]);
                mma_f16(oacc[2*nd+1], pa, &vf[2]);
            }
        }
        __syncthreads();
    }

    const float inv0 = 1.0f / (rsum0 + 1e-20f);
    const float inv1 = 1.0f / (rsum1 + 1e-20f);
    const size_t r0g = qrow0 + w * 16 + (lane >> 2);
    const size_t r1g = r0g + 8;
#pragma unroll
    for (int t = 0; t < 8; t++) {
        const int col = col0 + t * 8 + (lane & 3) * 2;
        *(uint32_t*)&o16[r0g * EE + col] = pack2h(oacc[t][0] * inv0, oacc[t][1] * inv0);
        *(uint32_t*)&o16[r1g * EE + col] = pack2h(oacc[t][2] * inv1, oacc[t][3] * inv1);
    }
}

// ============================================================================
// LayerNorm over E=1024; optional gated residual; optional fp16 output.
// ============================================================================
__global__ void __launch_bounds__(256) ln_kernel(
    const float* __restrict__ x, const float* __restrict__ f,
    const float* __restrict__ mask, const float* __restrict__ gamma,
    const float* __restrict__ beta, float* __restrict__ out,
    __half* __restrict__ out16, int useF)
{
    const int row = blockIdx.x;
    const int tid = threadIdx.x;

    float4 v4 = *(const float4*)&x[(size_t)row * EE + tid * 4];
    float v[4] = {v4.x, v4.y, v4.z, v4.w};

    if (useF) {
        const int b = row / SS, s = row % SS;
        const float gate = mask[((size_t)b * SS + (SS - 1)) * SS + s];
        float4 f4 = *(const float4*)&f[(size_t)row * EE + tid * 4];
        v[0] += f4.x * gate; v[1] += f4.y * gate;
        v[2] += f4.z * gate; v[3] += f4.w * gate;
    }

    float s1 = v[0] + v[1] + v[2] + v[3];
    float s2 = v[0]*v[0] + v[1]*v[1] + v[2]*v[2] + v[3]*v[3];
#pragma unroll
    for (int ofs = 16; ofs >= 1; ofs >>= 1) {
        s1 += __shfl_xor_sync(0xffffffffu, s1, ofs);
        s2 += __shfl_xor_sync(0xffffffffu, s2, ofs);
    }
    __shared__ float red1[8], red2[8];
    if ((tid & 31) == 0) { red1[tid >> 5] = s1; red2[tid >> 5] = s2; }
    __syncthreads();
    float t1 = 0.f, t2 = 0.f;
#pragma unroll
    for (int wv = 0; wv < 8; wv++) { t1 += red1[wv]; t2 += red2[wv]; }

    const float mean = t1 * (1.0f / EE);
    const float var  = t2 * (1.0f / EE) - mean * mean;
    const float inv  = rsqrtf(var + 1e-5f);

    float4 g4 = *(const float4*)&gamma[tid * 4];
    float4 b4 = *(const float4*)&beta[tid * 4];
    float o0 = (v[0] - mean) * inv * g4.x + b4.x;
    float o1 = (v[1] - mean) * inv * g4.y + b4.y;
    float o2 = (v[2] - mean) * inv * g4.z + b4.z;
    float o3 = (v[3] - mean) * inv * g4.w + b4.w;
    if (out)
        *(float4*)&out[(size_t)row * EE + tid * 4] = make_float4(o0, o1, o2, o3);
    if (out16) {
        const size_t go = (size_t)row * EE + tid * 4;
        *(uint32_t*)&out16[go]     = pack2h(o0, o1);
        *(uint32_t*)&out16[go + 2] = pack2h(o2, o3);
    }
}

// ============================================================================
extern "C" void kernel_launch(void* const* d_in, const int* in_sizes, int n_in,
                              void* d_out, int out_size)
{
    const float* h    = (const float*)d_in[0];
    const float* mask = (const float*)d_in[1];
    const float* wq   = (const float*)d_in[2];
    const float* wk   = (const float*)d_in[3];
    const float* wv   = (const float*)d_in[4];
    const float* wmh  = (const float*)d_in[5];
    const float* g1   = (const float*)d_in[6];
    const float* be1  = (const float*)d_in[7];
    const float* w1   = (const float*)d_in[8];
    const float* b1   = (const float*)d_in[9];
    const float* w2   = (const float*)d_in[10];
    const float* b2   = (const float*)d_in[11];
    const float* g2   = (const float*)d_in[12];
    const float* be2  = (const float*)d_in[13];
    float* out = (float*)d_out;

    float *h2, *a, *f;
    cudaGetSymbolAddress((void**)&h2, g_h2);
    cudaGetSymbolAddress((void**)&a,  g_a);
    cudaGetSymbolAddress((void**)&f,  g_f);

    __half *h16, *q16, *k16, *v16, *o16, *a16, *hid16;
    __half *w16q, *w16k, *w16v, *w16m, *w16a, *w16b;
    cudaGetSymbolAddress((void**)&h16, g_h16);
    cudaGetSymbolAddress((void**)&q16, g_q16);
    cudaGetSymbolAddress((void**)&k16, g_k16);
    cudaGetSymbolAddress((void**)&v16, g_v16);
    cudaGetSymbolAddress((void**)&o16, g_o16);
    cudaGetSymbolAddress((void**)&a16, g_a16);
    cudaGetSymbolAddress((void**)&hid16, g_hid16);
    cudaGetSymbolAddress((void**)&w16q, g_w16q); cudaGetSymbolAddress((void**)&w16k, g_w16k);
    cudaGetSymbolAddress((void**)&w16v, g_w16v); cudaGetSymbolAddress((void**)&w16m, g_w16m);
    cudaGetSymbolAddress((void**)&w16a, g_w16a); cudaGetSymbolAddress((void**)&w16b, g_w16b);

    cudaFuncSetAttribute(attn_mma, cudaFuncAttributeMaxDynamicSharedMemorySize, SMEM_ATT);
    cudaFuncSetAttribute(gemm_qkv, cudaFuncAttributeMaxDynamicSharedMemorySize, SMEM_MMA);
    cudaFuncSetAttribute(gemm_f16<3,0>, cudaFuncAttributeMaxDynamicSharedMemorySize, SMEM_MMA);
    cudaFuncSetAttribute(gemm_f16<2,1>, cudaFuncAttributeMaxDynamicSharedMemorySize, SMEM_MMA);
    cudaFuncSetAttribute(gemm_f16<1,0>, cudaFuncAttributeMaxDynamicSharedMemorySize, SMEM_MMA);

    // fp32 -> fp16 converts (input + weights)
    {
        int n4 = MTOK * EE / 4;
        cvt16_kernel<<<(n4 + 255) / 256, 256>>>(h, h16, n4);
        int w4 = EE * EE / 4;
        cvt16_kernel<<<(w4 + 255) / 256, 256>>>(wq,  w16q, w4);
        cvt16_kernel<<<(w4 + 255) / 256, 256>>>(wk,  w16k, w4);
        cvt16_kernel<<<(w4 + 255) / 256, 256>>>(wv,  w16v, w4);
        cvt16_kernel<<<(w4 + 255) / 256, 256>>>(wmh, w16m, w4);
        int v4a = HIDD * EE / 4;
        cvt16_kernel<<<(v4a + 255) / 256, 256>>>(w1, w16a, v4a);
        cvt16_kernel<<<(v4a + 255) / 256, 256>>>(w2, w16b, v4a);
    }

    dim3 blk(512);
    dim3 gQKV(EE / TN, MTOK / TM, 3);   // (4, 64, 3)
    dim3 gE(EE / TN, MTOK / TM);        // (4, 64)
    dim3 gHid(HIDD / TN, MTOK / TM);    // (16, 64)

    // QKV merged -> fp16
    gemm_qkv<<<gQKV, blk, SMEM_MMA>>>(h16, w16q, w16k, w16v,
                                      q16, k16, v16, MTOK, EE, EE);

    // attention -> o (fp16)
    attn_mma<<<dim3(SS / 64, HH, BB), dim3(128), SMEM_ATT>>>(mask, q16, k16, v16, o16);

    // mh + residual -> h2 (fp32)
    gemm_f16<3,0><<<gE, blk, SMEM_MMA>>>(o16, w16m, nullptr, h,
                                         h2, nullptr, MTOK, EE, EE);

    // attn_norm -> a fp32 + fp16
    ln_kernel<<<MTOK, 256>>>(h2, nullptr, nullptr, g1, be1, a, a16, 0);

    // FFN1 (+bias+GELU) -> hid fp16
    gemm_f16<2,1><<<gHid, blk, SMEM_MMA>>>(a16, w16a, b1, nullptr,
                                           nullptr, hid16, MTOK, HIDD, EE);
    // FFN2 (+bias) -> f fp32
    gemm_f16<1,0><<<gE, blk, SMEM_MMA>>>(hid16, w16b, b2, nullptr,
                                         f, nullptr, MTOK, EE, HIDD);

    // gated residual + ffn_norm -> out
    ln_kernel<<<MTOK, 256>>>(a, f, mask, g2, be2, out, nullptr, 1);
}